// round 12
// baseline (speedup 1.0000x reference)
#include <cuda_runtime.h>
#include <cuda_bf16.h>
#include <math.h>
#include <stdint.h>

#define B_SZ  4
#define NSEQ  1024
#define DIMM  2048
#define KDIM  2048
#define NH    16
#define NKV   4
#define DH    128
#define MTOT  (B_SZ * NSEQ)

// ---------------- scratch (device globals: no allocation allowed) ----------
__device__ float g_Qh[B_SZ * NH  * NSEQ * DH];     // fp32 [b,h,n,d]
__device__ float g_Kh[B_SZ * NKV * NSEQ * DH];
__device__ float g_Vh[B_SZ * NKV * NSEQ * DH];
__device__ __nv_bfloat16 g_xhi[MTOT * KDIM], g_xlo[MTOT * KDIM];
__device__ __nv_bfloat16 g_Wch[3072 * KDIM], g_Wcl[3072 * KDIM];   // Wq|Wk|Wv ^T
__device__ __nv_bfloat16 g_Woh[2048 * KDIM], g_Wol[2048 * KDIM];   // Wo ^T
__device__ __nv_bfloat16 g_Ohi[MTOT * DIMM], g_Olo[MTOT * DIMM];
__device__ __nv_bfloat16 g_Qbh[B_SZ * NH  * NSEQ * DH], g_Qbl[B_SZ * NH  * NSEQ * DH];
__device__ __nv_bfloat16 g_Kbh[B_SZ * NKV * NSEQ * DH], g_Kbl[B_SZ * NKV * NSEQ * DH];
__device__ __nv_bfloat16 g_Vbh[B_SZ * NKV * NSEQ * DH], g_Vbl[B_SZ * NKV * NSEQ * DH];
__device__ float g_cs[NSEQ * 64 * 2];              // rope cos/sin table

// ---------------- helpers ---------------------------------------------------
__device__ __forceinline__ uint32_t cvta_s(const void* p) {
    uint32_t a;
    asm("{ .reg .u64 t; cvta.to.shared.u64 t, %1; cvt.u32.u64 %0, t; }"
        : "=r"(a) : "l"(p));
    return a;
}
__device__ __forceinline__ void cp16(uint32_t dst, const void* src) {
    asm volatile("cp.async.cg.shared.global [%0], [%1], 16;"
                 :: "r"(dst), "l"(src) : "memory");
}
__device__ __forceinline__ void ldsm4(uint32_t* r, uint32_t addr) {
    asm volatile("ldmatrix.sync.aligned.m8n8.x4.shared.b16 {%0,%1,%2,%3}, [%4];"
                 : "=r"(r[0]), "=r"(r[1]), "=r"(r[2]), "=r"(r[3]) : "r"(addr));
}
__device__ __forceinline__ void ldsm4t(uint32_t* r, uint32_t addr) {
    asm volatile("ldmatrix.sync.aligned.m8n8.x4.trans.shared.b16 {%0,%1,%2,%3}, [%4];"
                 : "=r"(r[0]), "=r"(r[1]), "=r"(r[2]), "=r"(r[3]) : "r"(addr));
}
__device__ __forceinline__ void mma16816(float* d, const uint32_t* a,
                                         const uint32_t* b) {
    asm volatile(
        "mma.sync.aligned.m16n8k16.row.col.f32.bf16.bf16.f32 "
        "{%0,%1,%2,%3}, {%4,%5,%6,%7}, {%8,%9}, {%0,%1,%2,%3};"
        : "+f"(d[0]), "+f"(d[1]), "+f"(d[2]), "+f"(d[3])
        : "r"(a[0]), "r"(a[1]), "r"(a[2]), "r"(a[3]), "r"(b[0]), "r"(b[1]));
}
__device__ __forceinline__ void pack_hl(float v0, float v1,
                                        uint32_t& hi2, uint32_t& lo2) {
    __nv_bfloat16 h0 = __float2bfloat16(v0), h1 = __float2bfloat16(v1);
    __nv_bfloat162 hp(h0, h1);
    hi2 = *reinterpret_cast<uint32_t*>(&hp);
    __nv_bfloat162 lp(__float2bfloat16(v0 - __bfloat162float(h0)),
                      __float2bfloat16(v1 - __bfloat162float(h1)));
    lo2 = *reinterpret_cast<uint32_t*>(&lp);
}

// ---------------- prep kernels ---------------------------------------------
__global__ void rope_table(float* __restrict__ cs)
{
    int idx = blockIdx.x * blockDim.x + threadIdx.x;
    if (idx >= NSEQ * 64) return;
    int i = idx & 63, n = idx >> 6;
    double invf = exp(-(double)i * 0.14391156831212787);
    double s, c;
    sincos((double)n * invf, &s, &c);
    cs[idx * 2]     = (float)c;
    cs[idx * 2 + 1] = (float)s;
}

__global__ __launch_bounds__(256) void prep_split(const float* __restrict__ x,
                                                  __nv_bfloat16* __restrict__ hi,
                                                  __nv_bfloat16* __restrict__ lo,
                                                  int n4)
{
    int idx = blockIdx.x * blockDim.x + threadIdx.x;
    if (idx >= n4) return;
    float4 v = ((const float4*)x)[idx];
    __nv_bfloat16 h0 = __float2bfloat16(v.x), h1 = __float2bfloat16(v.y);
    __nv_bfloat16 h2 = __float2bfloat16(v.z), h3 = __float2bfloat16(v.w);
    __nv_bfloat162* hp = (__nv_bfloat162*)hi;
    __nv_bfloat162* lp = (__nv_bfloat162*)lo;
    hp[2*idx]   = __nv_bfloat162(h0, h1);
    hp[2*idx+1] = __nv_bfloat162(h2, h3);
    lp[2*idx]   = __nv_bfloat162(__float2bfloat16(v.x - __bfloat162float(h0)),
                                 __float2bfloat16(v.y - __bfloat162float(h1)));
    lp[2*idx+1] = __nv_bfloat162(__float2bfloat16(v.z - __bfloat162float(h2)),
                                 __float2bfloat16(v.w - __bfloat162float(h3)));
}

// weights -> W^T[n][k] bf16 hi/lo; Q/K/V go into the COMBINED buffer
// (rows 0..2047 = Wq, 2048..2559 = Wk, 2560..3071 = Wv), Wo separate.
__global__ __launch_bounds__(256) void wtrans_all(
    const float* __restrict__ Wq, const float* __restrict__ Wk,
    const float* __restrict__ Wv, const float* __restrict__ Wo,
    __nv_bfloat16* ch, __nv_bfloat16* cl,
    __nv_bfloat16* oh, __nv_bfloat16* ol)
{
    const float* W; __nv_bfloat16 *th, *tl; int N;
    switch (blockIdx.z) {
        case 0:  W = Wq; th = ch;               tl = cl;               N = 2048; break;
        case 1:  W = Wk; th = ch + 2048 * KDIM; tl = cl + 2048 * KDIM; N = 512;  break;
        case 2:  W = Wv; th = ch + 2560 * KDIM; tl = cl + 2560 * KDIM; N = 512;  break;
        default: W = Wo; th = oh;               tl = ol;               N = 2048; break;
    }
    int n0 = blockIdx.x * 32, k0 = blockIdx.y * 32;
    if (n0 >= N) return;
    __shared__ float t[32][33];
    int tx = threadIdx.x & 31, ty = threadIdx.x >> 5;
#pragma unroll
    for (int j = 0; j < 32; j += 8)
        t[ty + j][tx] = W[(size_t)(k0 + ty + j) * N + n0 + tx];
    __syncthreads();
#pragma unroll
    for (int j = 0; j < 32; j += 8) {
        float v = t[tx][ty + j];
        __nv_bfloat16 h = __float2bfloat16(v);
        size_t o = (size_t)(n0 + ty + j) * KDIM + k0 + tx;
        th[o] = h;
        tl[o] = __float2bfloat16(v - __bfloat162float(h));
    }
}

// ---------------- post_all: ropeQ + ropeK + V split (one launch) -----------
__global__ __launch_bounds__(256) void post_all(
    const float* __restrict__ Qh, const float* __restrict__ Kh,
    const float* __restrict__ Vh, const float* __restrict__ cs,
    __nv_bfloat16* __restrict__ Qbh, __nv_bfloat16* __restrict__ Qbl,
    __nv_bfloat16* __restrict__ Kbh, __nv_bfloat16* __restrict__ Kbl,
    __nv_bfloat16* __restrict__ Vbh, __nv_bfloat16* __restrict__ Vbl)
{
    const int blk = blockIdx.x, tid = threadIdx.x;
    if (blk < 20480) {
        const float* src; __nv_bfloat16 *hi, *lo; int idx;
        if (blk < 16384) { src = Qh; hi = Qbh; lo = Qbl; idx = blk * 256 + tid; }
        else             { src = Kh; hi = Kbh; lo = Kbl; idx = (blk - 16384) * 256 + tid; }
        int i   = idx & 63;
        int n   = (idx >> 6) & 1023;
        int bhd = idx >> 16;
        float2 v = ((const float2*)cs)[n * 64 + i];
        size_t o0 = (size_t)bhd * (NSEQ * DH) + n * DH + i;
        float t1 = src[o0], t2 = src[o0 + 64];
        float r0 = t1 * v.x - t2 * v.y;
        float r1 = t2 * v.x + t1 * v.y;
        __nv_bfloat16 b0 = __float2bfloat16(r0);
        __nv_bfloat16 b1 = __float2bfloat16(r1);
        hi[o0]      = b0; lo[o0]      = __float2bfloat16(r0 - __bfloat162float(b0));
        hi[o0 + 64] = b1; lo[o0 + 64] = __float2bfloat16(r1 - __bfloat162float(b1));
        return;
    }
    int idx = (blk - 20480) * 256 + tid;
    float4 v = ((const float4*)Vh)[idx];
    __nv_bfloat16 h0 = __float2bfloat16(v.x), h1 = __float2bfloat16(v.y);
    __nv_bfloat16 h2 = __float2bfloat16(v.z), h3 = __float2bfloat16(v.w);
    __nv_bfloat162* hp = (__nv_bfloat162*)Vbh;
    __nv_bfloat162* lp = (__nv_bfloat162*)Vbl;
    hp[2*idx]   = __nv_bfloat162(h0, h1);
    hp[2*idx+1] = __nv_bfloat162(h2, h3);
    lp[2*idx]   = __nv_bfloat162(__float2bfloat16(v.x - __bfloat162float(h0)),
                                 __float2bfloat16(v.y - __bfloat162float(h1)));
    lp[2*idx+1] = __nv_bfloat162(__float2bfloat16(v.z - __bfloat162float(h2)),
                                 __float2bfloat16(v.w - __bfloat162float(h3)));
}

// ---------------- mma.sync GEMM: 3-stage pipeline, 1 barrier/stage ---------
// 256 thr, 8 warps (4m x 2n), warp tile 32x64, CTA 128x128, k-stage 64.
// MODE 0: C = plain [M][Nglob] at col offset bn (output projection)
// MODE 1: QKV combined (N=3072): route tile to Qh/Kh/Vh head layout.
template <int MODE>
__global__ __launch_bounds__(256)
void gemm_mma(const __nv_bfloat16* __restrict__ Ahi, const __nv_bfloat16* __restrict__ Alo,
              const __nv_bfloat16* __restrict__ Bhi, const __nv_bfloat16* __restrict__ Blo,
              float* __restrict__ Cq, float* __restrict__ Ck, float* __restrict__ Cv,
              int Nglob)
{
    extern __shared__ __align__(16) char smem[];
    const uint32_t sb0 = cvta_s(smem);

    const int tid  = threadIdx.x;
    const int wid  = tid >> 5, lane = tid & 31;
    const int wm   = wid & 3,  wn   = wid >> 2;
    const int am   = wm * 32,  bn0  = wn * 64;
    const int bm   = blockIdx.y * 128, bn = blockIdx.x * 128;

    const __nv_bfloat16* srcs[4] = { Ahi + (size_t)bm * KDIM, Alo + (size_t)bm * KDIM,
                                     Bhi + (size_t)bn * KDIM, Blo + (size_t)bn * KDIM };

    const int lr[4] = { (tid + 0)   >> 3, (tid + 256) >> 3,
                        (tid + 512) >> 3, (tid + 768) >> 3 };
    const int lc[4] = { (tid + 0)   & 7,  (tid + 256) & 7,
                        (tid + 512) & 7,  (tid + 768) & 7 };

    float acc[2][8][4];
#pragma unroll
    for (int mi = 0; mi < 2; mi++)
#pragma unroll
        for (int ni = 0; ni < 8; ni++)
#pragma unroll
            for (int c = 0; c < 4; c++) acc[mi][ni][c] = 0.f;

    const int NT = KDIM / 64;   // 32 stages

    auto load_stage = [&](int s, int kt) {
        uint32_t sb = sb0 + s * 65536;
#pragma unroll
        for (int tt = 0; tt < 4; tt++) {
            const __nv_bfloat16* src = srcs[tt];
#pragma unroll
            for (int a = 0; a < 4; a++) {
                int r = lr[a], c4 = lc[a];
                uint32_t dst = sb + tt * 16384 + r * 128 + ((c4 ^ (r & 7)) << 4);
                cp16(dst, src + (size_t)r * KDIM + kt + c4 * 8);
            }
        }
        asm volatile("cp.async.commit_group;" ::: "memory");
    };

    load_stage(0, 0);
    load_stage(1, 64);

    int buf = 0;
    for (int it = 0; it < NT; ++it) {
        if (it + 1 < NT) {
            asm volatile("cp.async.wait_group 1;" ::: "memory");
        } else {
            asm volatile("cp.async.wait_group 0;" ::: "memory");
        }
        __syncthreads();     // stage `it` ready; all warps done with stage it-1
        if (it + 2 < NT) {
            int nb = buf + 2; if (nb >= 3) nb -= 3;
            load_stage(nb, (it + 2) * 64);
        }

        const uint32_t sb = sb0 + buf * 65536;
#pragma unroll
        for (int ks = 0; ks < 4; ks++) {
            uint32_t ah[2][4], al[2][4], bh[8][2], bl[8][2];
#pragma unroll
            for (int mi = 0; mi < 2; mi++) {
                int r  = am + mi * 16 + (lane & 15);
                int c4 = ks * 2 + (lane >> 4);
                uint32_t off = r * 128 + ((c4 ^ (r & 7)) << 4);
                ldsm4(ah[mi], sb + off);
                ldsm4(al[mi], sb + 16384 + off);
            }
#pragma unroll
            for (int nb2 = 0; nb2 < 4; nb2++) {
                int r  = bn0 + nb2 * 16 + (lane & 15);
                int c4 = ks * 2 + (lane >> 4);
                uint32_t off = r * 128 + ((c4 ^ (r & 7)) << 4);
                uint32_t t[4];
                ldsm4(t, sb + 32768 + off);
                bh[nb2*2][0] = t[0]; bh[nb2*2][1] = t[2];
                bh[nb2*2+1][0] = t[1]; bh[nb2*2+1][1] = t[3];
                ldsm4(t, sb + 49152 + off);
                bl[nb2*2][0] = t[0]; bl[nb2*2][1] = t[2];
                bl[nb2*2+1][0] = t[1]; bl[nb2*2+1][1] = t[3];
            }
#pragma unroll
            for (int mi = 0; mi < 2; mi++)
#pragma unroll
                for (int ni = 0; ni < 8; ni++) mma16816(acc[mi][ni], ah[mi], bh[ni]);
#pragma unroll
            for (int mi = 0; mi < 2; mi++)
#pragma unroll
                for (int ni = 0; ni < 8; ni++) mma16816(acc[mi][ni], al[mi], bh[ni]);
#pragma unroll
            for (int mi = 0; mi < 2; mi++)
#pragma unroll
                for (int ni = 0; ni < 8; ni++) mma16816(acc[mi][ni], ah[mi], bl[ni]);
        }
        if (++buf == 3) buf = 0;
    }

    // epilogue
    float* base; int h = 0, Hout = 0;
    if (MODE == 1) {
        if (bn < 2048)      { base = Cq; h = bn >> 7;          Hout = NH;  }
        else if (bn < 2560) { base = Ck; h = (bn - 2048) >> 7; Hout = NKV; }
        else                { base = Cv; h = (bn - 2560) >> 7; Hout = NKV; }
    } else {
        base = Cq;
    }
    const int g = lane >> 2, tig = lane & 3;
#pragma unroll
    for (int mi = 0; mi < 2; mi++) {
#pragma unroll
        for (int ni = 0; ni < 8; ni++) {
            int d   = bn0 + ni * 8 + tig * 2;
            int r0  = bm + am + mi * 16 + g;
            int r1  = r0 + 8;
            float* p0;
            float* p1;
            if (MODE == 1) {
                int b0 = r0 >> 10, n0 = r0 & 1023;
                int b1 = r1 >> 10, n1 = r1 & 1023;
                p0 = base + (((size_t)(b0 * Hout + h)) * NSEQ + n0) * DH + d;
                p1 = base + (((size_t)(b1 * Hout + h)) * NSEQ + n1) * DH + d;
            } else {
                p0 = base + (size_t)r0 * Nglob + bn + d;
                p1 = base + (size_t)r1 * Nglob + bn + d;
            }
            *(float2*)p0 = make_float2(acc[mi][ni][0], acc[mi][ni][1]);
            *(float2*)p1 = make_float2(acc[mi][ni][2], acc[mi][ni][3]);
        }
    }
}

// ---------------- tensor-core causal flash attention, P in registers -------
// q-tile 128 x kv-tile 64, 8 warps (warp = 16 q-rows).  (unchanged from R11)
__global__ __launch_bounds__(256)
void flash_tc(const __nv_bfloat16* __restrict__ Qh_, const __nv_bfloat16* __restrict__ Ql_,
              const __nv_bfloat16* __restrict__ Kh_, const __nv_bfloat16* __restrict__ Kl_,
              const __nv_bfloat16* __restrict__ Vh_, const __nv_bfloat16* __restrict__ Vl_,
              const float* __restrict__ hsc,
              __nv_bfloat16* __restrict__ Ohi, __nv_bfloat16* __restrict__ Olo)
{
    extern __shared__ __align__(16) char smc[];
    const uint32_t smb = cvta_s(smc);
    const int tid = threadIdx.x, wid = tid >> 5, lane = tid & 31;
    const int qb = 7 - blockIdx.x;
    const int bh = blockIdx.y, b = bh >> 4, h = bh & 15, kvh = h >> 2;
    const int m0 = wid * 16;
    const int g = lane >> 2, tig = lane & 3;
    const float scale = 0.08838834764831845f;

    const __nv_bfloat16* Qhg = Qh_ + ((size_t)(b * NH + h) * NSEQ + qb * 128) * DH;
    const __nv_bfloat16* Qlg = Ql_ + ((size_t)(b * NH + h) * NSEQ + qb * 128) * DH;
    const size_t kvb = (size_t)(b * NKV + kvh) * NSEQ * DH;

#pragma unroll
    for (int t = 0; t < 8; t++) {
        int e = tid + t * 256, r = e >> 4, c4 = e & 15;
        uint32_t off = r * 256 + ((c4 ^ (r & 7)) << 4);
        cp16(smb + off,         Qhg + r * DH + c4 * 8);
        cp16(smb + 32768 + off, Qlg + r * DH + c4 * 8);
    }
    auto ldkv = [&](int s, int kb) {
        const __nv_bfloat16* kh = Kh_ + kvb + (size_t)kb * 64 * DH;
        const __nv_bfloat16* kl = Kl_ + kvb + (size_t)kb * 64 * DH;
        const __nv_bfloat16* vh = Vh_ + kvb + (size_t)kb * 64 * DH;
        const __nv_bfloat16* vl = Vl_ + kvb + (size_t)kb * 64 * DH;
        uint32_t kd = smb + 65536  + s * 32768;
        uint32_t vd = smb + 131072 + s * 32768;
#pragma unroll
        for (int t = 0; t < 4; t++) {
            int e = tid + t * 256, r = e >> 4, c4 = e & 15;
            uint32_t off = r * 256 + ((c4 ^ (r & 7)) << 4);
            int go = r * DH + c4 * 8;
            cp16(kd + off,         kh + go);
            cp16(kd + 16384 + off, kl + go);
            cp16(vd + off,         vh + go);
            cp16(vd + 16384 + off, vl + go);
        }
        asm volatile("cp.async.commit_group;" ::: "memory");
    };
    ldkv(0, 0);

    float m_i[2] = {-1e30f, -1e30f}, l_i[2] = {0.f, 0.f};
    float o[16][4];
#pragma unroll
    for (int ni = 0; ni < 16; ni++)
#pragma unroll
        for (int c = 0; c < 4; c++) o[ni][c] = 0.f;

    const int kb_max = 2 * qb + 1;
    for (int kb = 0; kb <= kb_max; ++kb) {
        asm volatile("cp.async.wait_group 0;" ::: "memory");
        __syncthreads();
        if (kb < kb_max) ldkv((kb + 1) & 1, kb + 1);

        const uint32_t sK = smb + 65536  + (kb & 1) * 32768;
        const uint32_t sV = smb + 131072 + (kb & 1) * 32768;

        float sf[8][4];
#pragma unroll
        for (int ni = 0; ni < 8; ni++)
#pragma unroll
            for (int c = 0; c < 4; c++) sf[ni][c] = 0.f;

#pragma unroll
        for (int ks = 0; ks < 8; ks++) {
            uint32_t ah[4], al[4], bh2[8][2], bl2[8][2];
            {
                int r = m0 + (lane & 15), c4 = ks * 2 + (lane >> 4);
                uint32_t off = r * 256 + ((c4 ^ (r & 7)) << 4);
                ldsm4(ah, smb + off);
                ldsm4(al, smb + 32768 + off);
            }
#pragma unroll
            for (int nb = 0; nb < 4; nb++) {
                int r = nb * 16 + (lane & 15), c4 = ks * 2 + (lane >> 4);
                uint32_t off = r * 256 + ((c4 ^ (r & 7)) << 4);
                uint32_t t4r[4];
                ldsm4(t4r, sK + off);
                bh2[nb*2][0] = t4r[0]; bh2[nb*2][1] = t4r[2];
                bh2[nb*2+1][0] = t4r[1]; bh2[nb*2+1][1] = t4r[3];
                ldsm4(t4r, sK + 16384 + off);
                bl2[nb*2][0] = t4r[0]; bl2[nb*2][1] = t4r[2];
                bl2[nb*2+1][0] = t4r[1]; bl2[nb*2+1][1] = t4r[3];
            }
#pragma unroll
            for (int ni = 0; ni < 8; ni++) mma16816(sf[ni], ah, bh2[ni]);
#pragma unroll
            for (int ni = 0; ni < 8; ni++) mma16816(sf[ni], al, bh2[ni]);
#pragma unroll
            for (int ni = 0; ni < 8; ni++) mma16816(sf[ni], ah, bl2[ni]);
        }

        const bool near = (kb * 64 + 63) > (qb * 128 + m0);
#pragma unroll
        for (int rr = 0; rr < 2; rr++) {
            int row_g = qb * 128 + m0 + g + rr * 8;
            float mx = -1e30f;
#pragma unroll
            for (int ni = 0; ni < 8; ni++)
#pragma unroll
                for (int c = 0; c < 2; c++) {
                    float v = sf[ni][rr * 2 + c] * scale;
                    if (near && (kb * 64 + ni * 8 + tig * 2 + c) > row_g) v = -1e30f;
                    sf[ni][rr * 2 + c] = v;
                    mx = fmaxf(mx, v);
                }
            mx = fmaxf(mx, __shfl_xor_sync(0xffffffffu, mx, 1));
            mx = fmaxf(mx, __shfl_xor_sync(0xffffffffu, mx, 2));
            float mn    = fmaxf(m_i[rr], mx);
            float alpha = __expf(m_i[rr] - mn);
            m_i[rr] = mn;
            float rs = 0.f;
#pragma unroll
            for (int ni = 0; ni < 8; ni++)
#pragma unroll
                for (int c = 0; c < 2; c++) {
                    float p = __expf(sf[ni][rr * 2 + c] - mn);
                    sf[ni][rr * 2 + c] = p;
                    rs += p;
                }
            rs += __shfl_xor_sync(0xffffffffu, rs, 1);
            rs += __shfl_xor_sync(0xffffffffu, rs, 2);
            l_i[rr] = l_i[rr] * alpha + rs;
#pragma unroll
            for (int ni = 0; ni < 16; ni++) {
                o[ni][rr * 2]     *= alpha;
                o[ni][rr * 2 + 1] *= alpha;
            }
        }

#pragma unroll
        for (int ks = 0; ks < 4; ks++) {
            uint32_t ph[4], pl[4];
            pack_hl(sf[2*ks][0],   sf[2*ks][1],   ph[0], pl[0]);
            pack_hl(sf[2*ks][2],   sf[2*ks][3],   ph[1], pl[1]);
            pack_hl(sf[2*ks+1][0], sf[2*ks+1][1], ph[2], pl[2]);
            pack_hl(sf[2*ks+1][2], sf[2*ks+1][3], ph[3], pl[3]);
#pragma unroll
            for (int nb = 0; nb < 8; nb++) {
                int row = ks * 16 + (lane & 7) + ((lane & 16) >> 1);
                int ch  = nb * 2 + ((lane >> 3) & 1);
                uint32_t off = row * 256 + ((ch ^ (row & 7)) << 4);
                uint32_t t4r[4], bvh[2][2], bvl[2][2];
                ldsm4t(t4r, sV + off);
                bvh[0][0] = t4r[0]; bvh[0][1] = t4r[2];
                bvh[1][0] = t4r[1]; bvh[1][1] = t4r[3];
                ldsm4t(t4r, sV + 16384 + off);
                bvl[0][0] = t4r[0]; bvl[0][1] = t4r[2];
                bvl[1][0] = t4r[1]; bvl[1][1] = t4r[3];
                mma16816(o[nb*2],   ph, bvh[0]);
                mma16816(o[nb*2+1], ph, bvh[1]);
                mma16816(o[nb*2],   pl, bvh[0]);
                mma16816(o[nb*2+1], pl, bvh[1]);
                mma16816(o[nb*2],   ph, bvl[0]);
                mma16816(o[nb*2+1], ph, bvl[1]);
            }
        }
    }

    const float hval = hsc[h];
#pragma unroll
    for (int rr = 0; rr < 2; rr++) {
        float inv = hval / l_i[rr];
        int n = qb * 128 + m0 + g + rr * 8;
        size_t base = ((size_t)(b * NSEQ + n)) * DIMM + h * DH;
#pragma unroll
        for (int ni = 0; ni < 16; ni++) {
            int col = ni * 8 + tig * 2;
            float v0 = o[ni][rr * 2] * inv, v1 = o[ni][rr * 2 + 1] * inv;
            __nv_bfloat16 h0 = __float2bfloat16(v0), h1 = __float2bfloat16(v1);
            *(__nv_bfloat162*)(Ohi + base + col) = __nv_bfloat162(h0, h1);
            *(__nv_bfloat162*)(Olo + base + col) =
                __nv_bfloat162(__float2bfloat16(v0 - __bfloat162float(h0)),
                               __float2bfloat16(v1 - __bfloat162float(h1)));
        }
    }
}

// ---------------- launch ---------------------------------------------------
extern "C" void kernel_launch(void* const* d_in, const int* in_sizes, int n_in,
                              void* d_out, int out_size)
{
    const float* x   = (const float*)d_in[0];
    const float* Wq  = (const float*)d_in[1];
    const float* Wk  = (const float*)d_in[2];
    const float* Wv  = (const float*)d_in[3];
    const float* Wo  = (const float*)d_in[4];
    const float* hsc = (const float*)d_in[5];
    float* out = (float*)d_out;

    float *Qh, *Kh, *Vh, *cs;
    __nv_bfloat16 *xhi, *xlo, *Wch, *Wcl, *Woh, *Wol, *Ohi, *Olo;
    __nv_bfloat16 *Qbh, *Qbl, *Kbh, *Kbl, *Vbh, *Vbl;
    cudaGetSymbolAddress((void**)&Qh,  g_Qh);
    cudaGetSymbolAddress((void**)&Kh,  g_Kh);
    cudaGetSymbolAddress((void**)&Vh,  g_Vh);
    cudaGetSymbolAddress((void**)&cs,  g_cs);
    cudaGetSymbolAddress((void**)&xhi, g_xhi);  cudaGetSymbolAddress((void**)&xlo, g_xlo);
    cudaGetSymbolAddress((void**)&Wch, g_Wch);  cudaGetSymbolAddress((void**)&Wcl, g_Wcl);
    cudaGetSymbolAddress((void**)&Woh, g_Woh);  cudaGetSymbolAddress((void**)&Wol, g_Wol);
    cudaGetSymbolAddress((void**)&Ohi, g_Ohi);  cudaGetSymbolAddress((void**)&Olo, g_Olo);
    cudaGetSymbolAddress((void**)&Qbh, g_Qbh);  cudaGetSymbolAddress((void**)&Qbl, g_Qbl);
    cudaGetSymbolAddress((void**)&Kbh, g_Kbh);  cudaGetSymbolAddress((void**)&Kbl, g_Kbl);
    cudaGetSymbolAddress((void**)&Vbh, g_Vbh);  cudaGetSymbolAddress((void**)&Vbl, g_Vbl);

    // launches 1..3: prep
    rope_table<<<(NSEQ * 64 + 255) / 256, 256>>>(cs);
    prep_split<<<(MTOT * KDIM / 4 + 255) / 256, 256>>>(x, xhi, xlo, MTOT * KDIM / 4);
    wtrans_all<<<dim3(64, 64, 4), 256>>>(Wq, Wk, Wv, Wo, Wch, Wcl, Woh, Wol);

    // launch 4: merged QKV projection (N=3072, 768 CTAs)
    const int gsm = 196608;     // 3 stages x 64KB
    cudaFuncSetAttribute(gemm_mma<1>, cudaFuncAttributeMaxDynamicSharedMemorySize, gsm);
    cudaFuncSetAttribute(gemm_mma<0>, cudaFuncAttributeMaxDynamicSharedMemorySize, gsm);
    gemm_mma<1><<<dim3(24, 32), 256, gsm>>>(xhi, xlo, Wch, Wcl, Qh, Kh, Vh, 0);

    // launch 5: rope Q/K + V split
    post_all<<<22528, 256>>>(Qh, Kh, Vh, cs, Qbh, Qbl, Kbh, Kbl, Vbh, Vbl);

    // launch 6 (PROFILED): tensor-core flash attention
    const int fsm = 196608;
    cudaFuncSetAttribute(flash_tc, cudaFuncAttributeMaxDynamicSharedMemorySize, fsm);
    flash_tc<<<dim3(8, B_SZ * NH), 256, fsm>>>(Qbh, Qbl, Kbh, Kbl, Vbh, Vbl,
                                               hsc, Ohi, Olo);

    // launch 7: output projection
    gemm_mma<0><<<dim3(16, 32), 256, gsm>>>(Ohi, Olo, Woh, Wol, out, nullptr, nullptr, 2048);
}

// round 13
// speedup vs baseline: 1.0020x; 1.0020x over previous
#include <cuda_runtime.h>
#include <cuda_bf16.h>
#include <math.h>
#include <stdint.h>

#define B_SZ  4
#define NSEQ  1024
#define DIMM  2048
#define KDIM  2048
#define NH    16
#define NKV   4
#define DH    128
#define MTOT  (B_SZ * NSEQ)

// ---------------- scratch (device globals: no allocation allowed) ----------
__device__ float g_Qh[B_SZ * NH  * NSEQ * DH];     // fp32 [b,h,n,d]
__device__ float g_Kh[B_SZ * NKV * NSEQ * DH];
__device__ float g_Vh[B_SZ * NKV * NSEQ * DH];
__device__ __nv_bfloat16 g_xhi[MTOT * KDIM], g_xlo[MTOT * KDIM];
__device__ __nv_bfloat16 g_Wch[3072 * KDIM], g_Wcl[3072 * KDIM];   // Wq|Wk|Wv ^T
__device__ __nv_bfloat16 g_Woh[2048 * KDIM], g_Wol[2048 * KDIM];   // Wo ^T
__device__ __nv_bfloat16 g_Ohi[MTOT * DIMM], g_Olo[MTOT * DIMM];
__device__ __nv_bfloat16 g_Qbh[B_SZ * NH  * NSEQ * DH], g_Qbl[B_SZ * NH  * NSEQ * DH];
__device__ __nv_bfloat16 g_Kbh[B_SZ * NKV * NSEQ * DH], g_Kbl[B_SZ * NKV * NSEQ * DH];
__device__ __nv_bfloat16 g_Vbh[B_SZ * NKV * NSEQ * DH], g_Vbl[B_SZ * NKV * NSEQ * DH];
__device__ float g_cs[NSEQ * 64 * 2];              // rope cos/sin table

// ---------------- helpers ---------------------------------------------------
__device__ __forceinline__ uint32_t cvta_s(const void* p) {
    uint32_t a;
    asm("{ .reg .u64 t; cvta.to.shared.u64 t, %1; cvt.u32.u64 %0, t; }"
        : "=r"(a) : "l"(p));
    return a;
}
__device__ __forceinline__ void cp16(uint32_t dst, const void* src) {
    asm volatile("cp.async.cg.shared.global [%0], [%1], 16;"
                 :: "r"(dst), "l"(src) : "memory");
}
__device__ __forceinline__ void ldsm4(uint32_t* r, uint32_t addr) {
    asm volatile("ldmatrix.sync.aligned.m8n8.x4.shared.b16 {%0,%1,%2,%3}, [%4];"
                 : "=r"(r[0]), "=r"(r[1]), "=r"(r[2]), "=r"(r[3]) : "r"(addr));
}
__device__ __forceinline__ void ldsm4t(uint32_t* r, uint32_t addr) {
    asm volatile("ldmatrix.sync.aligned.m8n8.x4.trans.shared.b16 {%0,%1,%2,%3}, [%4];"
                 : "=r"(r[0]), "=r"(r[1]), "=r"(r[2]), "=r"(r[3]) : "r"(addr));
}
__device__ __forceinline__ void mma16816(float* d, const uint32_t* a,
                                         const uint32_t* b) {
    asm volatile(
        "mma.sync.aligned.m16n8k16.row.col.f32.bf16.bf16.f32 "
        "{%0,%1,%2,%3}, {%4,%5,%6,%7}, {%8,%9}, {%0,%1,%2,%3};"
        : "+f"(d[0]), "+f"(d[1]), "+f"(d[2]), "+f"(d[3])
        : "r"(a[0]), "r"(a[1]), "r"(a[2]), "r"(a[3]), "r"(b[0]), "r"(b[1]));
}
__device__ __forceinline__ void pack_hl(float v0, float v1,
                                        uint32_t& hi2, uint32_t& lo2) {
    __nv_bfloat16 h0 = __float2bfloat16(v0), h1 = __float2bfloat16(v1);
    __nv_bfloat162 hp(h0, h1);
    hi2 = *reinterpret_cast<uint32_t*>(&hp);
    __nv_bfloat162 lp(__float2bfloat16(v0 - __bfloat162float(h0)),
                      __float2bfloat16(v1 - __bfloat162float(h1)));
    lo2 = *reinterpret_cast<uint32_t*>(&lp);
}

// ---------------- prep kernels ---------------------------------------------
__global__ void rope_table(float* __restrict__ cs)
{
    int idx = blockIdx.x * blockDim.x + threadIdx.x;
    if (idx >= NSEQ * 64) return;
    int i = idx & 63, n = idx >> 6;
    double invf = exp(-(double)i * 0.14391156831212787);
    double s, c;
    sincos((double)n * invf, &s, &c);
    cs[idx * 2]     = (float)c;
    cs[idx * 2 + 1] = (float)s;
}

__global__ __launch_bounds__(256) void prep_split(const float* __restrict__ x,
                                                  __nv_bfloat16* __restrict__ hi,
                                                  __nv_bfloat16* __restrict__ lo,
                                                  int n4)
{
    int idx = blockIdx.x * blockDim.x + threadIdx.x;
    if (idx >= n4) return;
    float4 v = ((const float4*)x)[idx];
    __nv_bfloat16 h0 = __float2bfloat16(v.x), h1 = __float2bfloat16(v.y);
    __nv_bfloat16 h2 = __float2bfloat16(v.z), h3 = __float2bfloat16(v.w);
    __nv_bfloat162* hp = (__nv_bfloat162*)hi;
    __nv_bfloat162* lp = (__nv_bfloat162*)lo;
    hp[2*idx]   = __nv_bfloat162(h0, h1);
    hp[2*idx+1] = __nv_bfloat162(h2, h3);
    lp[2*idx]   = __nv_bfloat162(__float2bfloat16(v.x - __bfloat162float(h0)),
                                 __float2bfloat16(v.y - __bfloat162float(h1)));
    lp[2*idx+1] = __nv_bfloat162(__float2bfloat16(v.z - __bfloat162float(h2)),
                                 __float2bfloat16(v.w - __bfloat162float(h3)));
}

// weights -> W^T[n][k] bf16 hi/lo; Q/K/V into combined buffer, Wo separate.
__global__ __launch_bounds__(256) void wtrans_all(
    const float* __restrict__ Wq, const float* __restrict__ Wk,
    const float* __restrict__ Wv, const float* __restrict__ Wo,
    __nv_bfloat16* ch, __nv_bfloat16* cl,
    __nv_bfloat16* oh, __nv_bfloat16* ol)
{
    const float* W; __nv_bfloat16 *th, *tl; int N;
    switch (blockIdx.z) {
        case 0:  W = Wq; th = ch;               tl = cl;               N = 2048; break;
        case 1:  W = Wk; th = ch + 2048 * KDIM; tl = cl + 2048 * KDIM; N = 512;  break;
        case 2:  W = Wv; th = ch + 2560 * KDIM; tl = cl + 2560 * KDIM; N = 512;  break;
        default: W = Wo; th = oh;               tl = ol;               N = 2048; break;
    }
    int n0 = blockIdx.x * 32, k0 = blockIdx.y * 32;
    if (n0 >= N) return;
    __shared__ float t[32][33];
    int tx = threadIdx.x & 31, ty = threadIdx.x >> 5;
#pragma unroll
    for (int j = 0; j < 32; j += 8)
        t[ty + j][tx] = W[(size_t)(k0 + ty + j) * N + n0 + tx];
    __syncthreads();
#pragma unroll
    for (int j = 0; j < 32; j += 8) {
        float v = t[tx][ty + j];
        __nv_bfloat16 h = __float2bfloat16(v);
        size_t o = (size_t)(n0 + ty + j) * KDIM + k0 + tx;
        th[o] = h;
        tl[o] = __float2bfloat16(v - __bfloat162float(h));
    }
}

// ---------------- post_all: ropeQ + ropeK + V split (one launch) -----------
__global__ __launch_bounds__(256) void post_all(
    const float* __restrict__ Qh, const float* __restrict__ Kh,
    const float* __restrict__ Vh, const float* __restrict__ cs,
    __nv_bfloat16* __restrict__ Qbh, __nv_bfloat16* __restrict__ Qbl,
    __nv_bfloat16* __restrict__ Kbh, __nv_bfloat16* __restrict__ Kbl,
    __nv_bfloat16* __restrict__ Vbh, __nv_bfloat16* __restrict__ Vbl)
{
    const int blk = blockIdx.x, tid = threadIdx.x;
    if (blk < 20480) {
        const float* src; __nv_bfloat16 *hi, *lo; int idx;
        if (blk < 16384) { src = Qh; hi = Qbh; lo = Qbl; idx = blk * 256 + tid; }
        else             { src = Kh; hi = Kbh; lo = Kbl; idx = (blk - 16384) * 256 + tid; }
        int i   = idx & 63;
        int n   = (idx >> 6) & 1023;
        int bhd = idx >> 16;
        float2 v = ((const float2*)cs)[n * 64 + i];
        size_t o0 = (size_t)bhd * (NSEQ * DH) + n * DH + i;
        float t1 = src[o0], t2 = src[o0 + 64];
        float r0 = t1 * v.x - t2 * v.y;
        float r1 = t2 * v.x + t1 * v.y;
        __nv_bfloat16 b0 = __float2bfloat16(r0);
        __nv_bfloat16 b1 = __float2bfloat16(r1);
        hi[o0]      = b0; lo[o0]      = __float2bfloat16(r0 - __bfloat162float(b0));
        hi[o0 + 64] = b1; lo[o0 + 64] = __float2bfloat16(r1 - __bfloat162float(b1));
        return;
    }
    int idx = (blk - 20480) * 256 + tid;
    float4 v = ((const float4*)Vh)[idx];
    __nv_bfloat16 h0 = __float2bfloat16(v.x), h1 = __float2bfloat16(v.y);
    __nv_bfloat16 h2 = __float2bfloat16(v.z), h3 = __float2bfloat16(v.w);
    __nv_bfloat162* hp = (__nv_bfloat162*)Vbh;
    __nv_bfloat162* lp = (__nv_bfloat162*)Vbl;
    hp[2*idx]   = __nv_bfloat162(h0, h1);
    hp[2*idx+1] = __nv_bfloat162(h2, h3);
    lp[2*idx]   = __nv_bfloat162(__float2bfloat16(v.x - __bfloat162float(h0)),
                                 __float2bfloat16(v.y - __bfloat162float(h1)));
    lp[2*idx+1] = __nv_bfloat162(__float2bfloat16(v.z - __bfloat162float(h2)),
                                 __float2bfloat16(v.w - __bfloat162float(h3)));
}

// ---------------- mma.sync GEMM: 3-stage cp.async + fragment double-buffer -
// 256 thr, 8 warps (4m x 2n), warp tile 32x64, CTA 128x128, k-stage 64.
// MODE 0: C plain [M][Nglob]; MODE 1: QKV combined (route to head layout).
template <int MODE>
__global__ __launch_bounds__(256)
void gemm_mma(const __nv_bfloat16* __restrict__ Ahi, const __nv_bfloat16* __restrict__ Alo,
              const __nv_bfloat16* __restrict__ Bhi, const __nv_bfloat16* __restrict__ Blo,
              float* __restrict__ Cq, float* __restrict__ Ck, float* __restrict__ Cv,
              int Nglob)
{
    extern __shared__ __align__(16) char smem[];
    const uint32_t sb0 = cvta_s(smem);

    const int tid  = threadIdx.x;
    const int wid  = tid >> 5, lane = tid & 31;
    const int wm   = wid & 3,  wn   = wid >> 2;
    const int am   = wm * 32,  bn0  = wn * 64;
    const int bm   = blockIdx.y * 128, bn = blockIdx.x * 128;

    const __nv_bfloat16* srcs[4] = { Ahi + (size_t)bm * KDIM, Alo + (size_t)bm * KDIM,
                                     Bhi + (size_t)bn * KDIM, Blo + (size_t)bn * KDIM };

    const int lr[4] = { (tid + 0)   >> 3, (tid + 256) >> 3,
                        (tid + 512) >> 3, (tid + 768) >> 3 };
    const int lc[4] = { (tid + 0)   & 7,  (tid + 256) & 7,
                        (tid + 512) & 7,  (tid + 768) & 7 };

    float acc[2][8][4];
#pragma unroll
    for (int mi = 0; mi < 2; mi++)
#pragma unroll
        for (int ni = 0; ni < 8; ni++)
#pragma unroll
            for (int c = 0; c < 4; c++) acc[mi][ni][c] = 0.f;

    const int NT = KDIM / 64;   // 32 stages

    auto load_stage = [&](int s, int kt) {
        uint32_t sb = sb0 + s * 65536;
#pragma unroll
        for (int tt = 0; tt < 4; tt++) {
            const __nv_bfloat16* src = srcs[tt];
#pragma unroll
            for (int a = 0; a < 4; a++) {
                int r = lr[a], c4 = lc[a];
                uint32_t dst = sb + tt * 16384 + r * 128 + ((c4 ^ (r & 7)) << 4);
                cp16(dst, src + (size_t)r * KDIM + kt + c4 * 8);
            }
        }
        asm volatile("cp.async.commit_group;" ::: "memory");
    };

    // double-buffered register fragments (pb = 0/1)
    uint32_t ahf[2][2][4], alf[2][2][4], bhf[2][8][2], blf[2][8][2];
    auto ld_frags = [&](uint32_t sb, int ks, int pb) {
#pragma unroll
        for (int mi = 0; mi < 2; mi++) {
            int r  = am + mi * 16 + (lane & 15);
            int c4 = ks * 2 + (lane >> 4);
            uint32_t off = r * 128 + ((c4 ^ (r & 7)) << 4);
            ldsm4(ahf[pb][mi], sb + off);
            ldsm4(alf[pb][mi], sb + 16384 + off);
        }
#pragma unroll
        for (int nb2 = 0; nb2 < 4; nb2++) {
            int r  = bn0 + nb2 * 16 + (lane & 15);
            int c4 = ks * 2 + (lane >> 4);
            uint32_t off = r * 128 + ((c4 ^ (r & 7)) << 4);
            uint32_t t[4];
            ldsm4(t, sb + 32768 + off);
            bhf[pb][nb2*2][0]   = t[0]; bhf[pb][nb2*2][1]   = t[2];
            bhf[pb][nb2*2+1][0] = t[1]; bhf[pb][nb2*2+1][1] = t[3];
            ldsm4(t, sb + 49152 + off);
            blf[pb][nb2*2][0]   = t[0]; blf[pb][nb2*2][1]   = t[2];
            blf[pb][nb2*2+1][0] = t[1]; blf[pb][nb2*2+1][1] = t[3];
        }
    };

    load_stage(0, 0);
    load_stage(1, 64);

    int buf = 0;
    for (int it = 0; it < NT; ++it) {
        if (it + 1 < NT) {
            asm volatile("cp.async.wait_group 1;" ::: "memory");
        } else {
            asm volatile("cp.async.wait_group 0;" ::: "memory");
        }
        __syncthreads();     // stage `it` ready; all warps done with stage it-1
        if (it + 2 < NT) {
            int nb = buf + 2; if (nb >= 3) nb -= 3;
            load_stage(nb, (it + 2) * 64);
        }

        const uint32_t sb = sb0 + buf * 65536;
        ld_frags(sb, 0, 0);
#pragma unroll
        for (int ks = 0; ks < 4; ks++) {
            const int cur = ks & 1;
            if (ks < 3) ld_frags(sb, ks + 1, cur ^ 1);   // prefetch next chunk
#pragma unroll
            for (int mi = 0; mi < 2; mi++)
#pragma unroll
                for (int ni = 0; ni < 8; ni++)
                    mma16816(acc[mi][ni], ahf[cur][mi], bhf[cur][ni]);
#pragma unroll
            for (int mi = 0; mi < 2; mi++)
#pragma unroll
                for (int ni = 0; ni < 8; ni++)
                    mma16816(acc[mi][ni], alf[cur][mi], bhf[cur][ni]);
#pragma unroll
            for (int mi = 0; mi < 2; mi++)
#pragma unroll
                for (int ni = 0; ni < 8; ni++)
                    mma16816(acc[mi][ni], ahf[cur][mi], blf[cur][ni]);
        }
        if (++buf == 3) buf = 0;
    }

    // epilogue
    float* base; int h = 0, Hout = 0;
    if (MODE == 1) {
        if (bn < 2048)      { base = Cq; h = bn >> 7;          Hout = NH;  }
        else if (bn < 2560) { base = Ck; h = (bn - 2048) >> 7; Hout = NKV; }
        else                { base = Cv; h = (bn - 2560) >> 7; Hout = NKV; }
    } else {
        base = Cq;
    }
    const int g = lane >> 2, tig = lane & 3;
#pragma unroll
    for (int mi = 0; mi < 2; mi++) {
#pragma unroll
        for (int ni = 0; ni < 8; ni++) {
            int d   = bn0 + ni * 8 + tig * 2;
            int r0  = bm + am + mi * 16 + g;
            int r1  = r0 + 8;
            float* p0;
            float* p1;
            if (MODE == 1) {
                int b0 = r0 >> 10, n0 = r0 & 1023;
                int b1 = r1 >> 10, n1 = r1 & 1023;
                p0 = base + (((size_t)(b0 * Hout + h)) * NSEQ + n0) * DH + d;
                p1 = base + (((size_t)(b1 * Hout + h)) * NSEQ + n1) * DH + d;
            } else {
                p0 = base + (size_t)r0 * Nglob + bn + d;
                p1 = base + (size_t)r1 * Nglob + bn + d;
            }
            *(float2*)p0 = make_float2(acc[mi][ni][0], acc[mi][ni][1]);
            *(float2*)p1 = make_float2(acc[mi][ni][2], acc[mi][ni][3]);
        }
    }
}

// ---------------- tensor-core causal flash attention, P in registers -------
// q-tile 128 x kv-tile 64, 8 warps (warp = 16 q-rows).  (unchanged from R11)
__global__ __launch_bounds__(256)
void flash_tc(const __nv_bfloat16* __restrict__ Qh_, const __nv_bfloat16* __restrict__ Ql_,
              const __nv_bfloat16* __restrict__ Kh_, const __nv_bfloat16* __restrict__ Kl_,
              const __nv_bfloat16* __restrict__ Vh_, const __nv_bfloat16* __restrict__ Vl_,
              const float* __restrict__ hsc,
              __nv_bfloat16* __restrict__ Ohi, __nv_bfloat16* __restrict__ Olo)
{
    extern __shared__ __align__(16) char smc[];
    const uint32_t smb = cvta_s(smc);
    const int tid = threadIdx.x, wid = tid >> 5, lane = tid & 31;
    const int qb = 7 - blockIdx.x;
    const int bh = blockIdx.y, b = bh >> 4, h = bh & 15, kvh = h >> 2;
    const int m0 = wid * 16;
    const int g = lane >> 2, tig = lane & 3;
    const float scale = 0.08838834764831845f;

    const __nv_bfloat16* Qhg = Qh_ + ((size_t)(b * NH + h) * NSEQ + qb * 128) * DH;
    const __nv_bfloat16* Qlg = Ql_ + ((size_t)(b * NH + h) * NSEQ + qb * 128) * DH;
    const size_t kvb = (size_t)(b * NKV + kvh) * NSEQ * DH;

#pragma unroll
    for (int t = 0; t < 8; t++) {
        int e = tid + t * 256, r = e >> 4, c4 = e & 15;
        uint32_t off = r * 256 + ((c4 ^ (r & 7)) << 4);
        cp16(smb + off,         Qhg + r * DH + c4 * 8);
        cp16(smb + 32768 + off, Qlg + r * DH + c4 * 8);
    }
    auto ldkv = [&](int s, int kb) {
        const __nv_bfloat16* kh = Kh_ + kvb + (size_t)kb * 64 * DH;
        const __nv_bfloat16* kl = Kl_ + kvb + (size_t)kb * 64 * DH;
        const __nv_bfloat16* vh = Vh_ + kvb + (size_t)kb * 64 * DH;
        const __nv_bfloat16* vl = Vl_ + kvb + (size_t)kb * 64 * DH;
        uint32_t kd = smb + 65536  + s * 32768;
        uint32_t vd = smb + 131072 + s * 32768;
#pragma unroll
        for (int t = 0; t < 4; t++) {
            int e = tid + t * 256, r = e >> 4, c4 = e & 15;
            uint32_t off = r * 256 + ((c4 ^ (r & 7)) << 4);
            int go = r * DH + c4 * 8;
            cp16(kd + off,         kh + go);
            cp16(kd + 16384 + off, kl + go);
            cp16(vd + off,         vh + go);
            cp16(vd + 16384 + off, vl + go);
        }
        asm volatile("cp.async.commit_group;" ::: "memory");
    };
    ldkv(0, 0);

    float m_i[2] = {-1e30f, -1e30f}, l_i[2] = {0.f, 0.f};
    float o[16][4];
#pragma unroll
    for (int ni = 0; ni < 16; ni++)
#pragma unroll
        for (int c = 0; c < 4; c++) o[ni][c] = 0.f;

    const int kb_max = 2 * qb + 1;
    for (int kb = 0; kb <= kb_max; ++kb) {
        asm volatile("cp.async.wait_group 0;" ::: "memory");
        __syncthreads();
        if (kb < kb_max) ldkv((kb + 1) & 1, kb + 1);

        const uint32_t sK = smb + 65536  + (kb & 1) * 32768;
        const uint32_t sV = smb + 131072 + (kb & 1) * 32768;

        float sf[8][4];
#pragma unroll
        for (int ni = 0; ni < 8; ni++)
#pragma unroll
            for (int c = 0; c < 4; c++) sf[ni][c] = 0.f;

#pragma unroll
        for (int ks = 0; ks < 8; ks++) {
            uint32_t ah[4], al[4], bh2[8][2], bl2[8][2];
            {
                int r = m0 + (lane & 15), c4 = ks * 2 + (lane >> 4);
                uint32_t off = r * 256 + ((c4 ^ (r & 7)) << 4);
                ldsm4(ah, smb + off);
                ldsm4(al, smb + 32768 + off);
            }
#pragma unroll
            for (int nb = 0; nb < 4; nb++) {
                int r = nb * 16 + (lane & 15), c4 = ks * 2 + (lane >> 4);
                uint32_t off = r * 256 + ((c4 ^ (r & 7)) << 4);
                uint32_t t4r[4];
                ldsm4(t4r, sK + off);
                bh2[nb*2][0] = t4r[0]; bh2[nb*2][1] = t4r[2];
                bh2[nb*2+1][0] = t4r[1]; bh2[nb*2+1][1] = t4r[3];
                ldsm4(t4r, sK + 16384 + off);
                bl2[nb*2][0] = t4r[0]; bl2[nb*2][1] = t4r[2];
                bl2[nb*2+1][0] = t4r[1]; bl2[nb*2+1][1] = t4r[3];
            }
#pragma unroll
            for (int ni = 0; ni < 8; ni++) mma16816(sf[ni], ah, bh2[ni]);
#pragma unroll
            for (int ni = 0; ni < 8; ni++) mma16816(sf[ni], al, bh2[ni]);
#pragma unroll
            for (int ni = 0; ni < 8; ni++) mma16816(sf[ni], ah, bl2[ni]);
        }

        const bool near = (kb * 64 + 63) > (qb * 128 + m0);
#pragma unroll
        for (int rr = 0; rr < 2; rr++) {
            int row_g = qb * 128 + m0 + g + rr * 8;
            float mx = -1e30f;
#pragma unroll
            for (int ni = 0; ni < 8; ni++)
#pragma unroll
                for (int c = 0; c < 2; c++) {
                    float v = sf[ni][rr * 2 + c] * scale;
                    if (near && (kb * 64 + ni * 8 + tig * 2 + c) > row_g) v = -1e30f;
                    sf[ni][rr * 2 + c] = v;
                    mx = fmaxf(mx, v);
                }
            mx = fmaxf(mx, __shfl_xor_sync(0xffffffffu, mx, 1));
            mx = fmaxf(mx, __shfl_xor_sync(0xffffffffu, mx, 2));
            float mn    = fmaxf(m_i[rr], mx);
            float alpha = __expf(m_i[rr] - mn);
            m_i[rr] = mn;
            float rs = 0.f;
#pragma unroll
            for (int ni = 0; ni < 8; ni++)
#pragma unroll
                for (int c = 0; c < 2; c++) {
                    float p = __expf(sf[ni][rr * 2 + c] - mn);
                    sf[ni][rr * 2 + c] = p;
                    rs += p;
                }
            rs += __shfl_xor_sync(0xffffffffu, rs, 1);
            rs += __shfl_xor_sync(0xffffffffu, rs, 2);
            l_i[rr] = l_i[rr] * alpha + rs;
#pragma unroll
            for (int ni = 0; ni < 16; ni++) {
                o[ni][rr * 2]     *= alpha;
                o[ni][rr * 2 + 1] *= alpha;
            }
        }

#pragma unroll
        for (int ks = 0; ks < 4; ks++) {
            uint32_t ph[4], pl[4];
            pack_hl(sf[2*ks][0],   sf[2*ks][1],   ph[0], pl[0]);
            pack_hl(sf[2*ks][2],   sf[2*ks][3],   ph[1], pl[1]);
            pack_hl(sf[2*ks+1][0], sf[2*ks+1][1], ph[2], pl[2]);
            pack_hl(sf[2*ks+1][2], sf[2*ks+1][3], ph[3], pl[3]);
#pragma unroll
            for (int nb = 0; nb < 8; nb++) {
                int row = ks * 16 + (lane & 7) + ((lane & 16) >> 1);
                int ch  = nb * 2 + ((lane >> 3) & 1);
                uint32_t off = row * 256 + ((ch ^ (row & 7)) << 4);
                uint32_t t4r[4], bvh[2][2], bvl[2][2];
                ldsm4t(t4r, sV + off);
                bvh[0][0] = t4r[0]; bvh[0][1] = t4r[2];
                bvh[1][0] = t4r[1]; bvh[1][1] = t4r[3];
                ldsm4t(t4r, sV + 16384 + off);
                bvl[0][0] = t4r[0]; bvl[0][1] = t4r[2];
                bvl[1][0] = t4r[1]; bvl[1][1] = t4r[3];
                mma16816(o[nb*2],   ph, bvh[0]);
                mma16816(o[nb*2+1], ph, bvh[1]);
                mma16816(o[nb*2],   pl, bvh[0]);
                mma16816(o[nb*2+1], pl, bvh[1]);
                mma16816(o[nb*2],   ph, bvl[0]);
                mma16816(o[nb*2+1], ph, bvl[1]);
            }
        }
    }

    const float hval = hsc[h];
#pragma unroll
    for (int rr = 0; rr < 2; rr++) {
        float inv = hval / l_i[rr];
        int n = qb * 128 + m0 + g + rr * 8;
        size_t base = ((size_t)(b * NSEQ + n)) * DIMM + h * DH;
#pragma unroll
        for (int ni = 0; ni < 16; ni++) {
            int col = ni * 8 + tig * 2;
            float v0 = o[ni][rr * 2] * inv, v1 = o[ni][rr * 2 + 1] * inv;
            __nv_bfloat16 h0 = __float2bfloat16(v0), h1 = __float2bfloat16(v1);
            *(__nv_bfloat162*)(Ohi + base + col) = __nv_bfloat162(h0, h1);
            *(__nv_bfloat162*)(Olo + base + col) =
                __nv_bfloat162(__float2bfloat16(v0 - __bfloat162float(h0)),
                               __float2bfloat16(v1 - __bfloat162float(h1)));
        }
    }
}

// ---------------- launch ---------------------------------------------------
extern "C" void kernel_launch(void* const* d_in, const int* in_sizes, int n_in,
                              void* d_out, int out_size)
{
    const float* x   = (const float*)d_in[0];
    const float* Wq  = (const float*)d_in[1];
    const float* Wk  = (const float*)d_in[2];
    const float* Wv  = (const float*)d_in[3];
    const float* Wo  = (const float*)d_in[4];
    const float* hsc = (const float*)d_in[5];
    float* out = (float*)d_out;

    float *Qh, *Kh, *Vh, *cs;
    __nv_bfloat16 *xhi, *xlo, *Wch, *Wcl, *Woh, *Wol, *Ohi, *Olo;
    __nv_bfloat16 *Qbh, *Qbl, *Kbh, *Kbl, *Vbh, *Vbl;
    cudaGetSymbolAddress((void**)&Qh,  g_Qh);
    cudaGetSymbolAddress((void**)&Kh,  g_Kh);
    cudaGetSymbolAddress((void**)&Vh,  g_Vh);
    cudaGetSymbolAddress((void**)&cs,  g_cs);
    cudaGetSymbolAddress((void**)&xhi, g_xhi);  cudaGetSymbolAddress((void**)&xlo, g_xlo);
    cudaGetSymbolAddress((void**)&Wch, g_Wch);  cudaGetSymbolAddress((void**)&Wcl, g_Wcl);
    cudaGetSymbolAddress((void**)&Woh, g_Woh);  cudaGetSymbolAddress((void**)&Wol, g_Wol);
    cudaGetSymbolAddress((void**)&Ohi, g_Ohi);  cudaGetSymbolAddress((void**)&Olo, g_Olo);
    cudaGetSymbolAddress((void**)&Qbh, g_Qbh);  cudaGetSymbolAddress((void**)&Qbl, g_Qbl);
    cudaGetSymbolAddress((void**)&Kbh, g_Kbh);  cudaGetSymbolAddress((void**)&Kbl, g_Kbl);
    cudaGetSymbolAddress((void**)&Vbh, g_Vbh);  cudaGetSymbolAddress((void**)&Vbl, g_Vbl);

    // launches 1..3: prep
    rope_table<<<(NSEQ * 64 + 255) / 256, 256>>>(cs);
    prep_split<<<(MTOT * KDIM / 4 + 255) / 256, 256>>>(x, xhi, xlo, MTOT * KDIM / 4);
    wtrans_all<<<dim3(64, 64, 4), 256>>>(Wq, Wk, Wv, Wo, Wch, Wcl, Woh, Wol);

    // launch 4 (PROFILED SLOT): merged QKV projection (N=3072, 768 CTAs)
    const int gsm = 196608;     // 3 stages x 64KB
    cudaFuncSetAttribute(gemm_mma<1>, cudaFuncAttributeMaxDynamicSharedMemorySize, gsm);
    cudaFuncSetAttribute(gemm_mma<0>, cudaFuncAttributeMaxDynamicSharedMemorySize, gsm);
    gemm_mma<1><<<dim3(24, 32), 256, gsm>>>(xhi, xlo, Wch, Wcl, Qh, Kh, Vh, 0);

    // launch 5: rope Q/K + V split
    post_all<<<22528, 256>>>(Qh, Kh, Vh, cs, Qbh, Qbl, Kbh, Kbl, Vbh, Vbl);

    // launch 6: tensor-core flash attention
    const int fsm = 196608;
    cudaFuncSetAttribute(flash_tc, cudaFuncAttributeMaxDynamicSharedMemorySize, fsm);
    flash_tc<<<dim3(8, B_SZ * NH), 256, fsm>>>(Qbh, Qbl, Kbh, Kbl, Vbh, Vbl,
                                               hsc, Ohi, Olo);

    // launch 7: output projection
    gemm_mma<0><<<dim3(16, 32), 256, gsm>>>(Ohi, Olo, Woh, Wol, out, nullptr, nullptr, 2048);
}

// round 14
// speedup vs baseline: 1.0894x; 1.0872x over previous
#include <cuda_runtime.h>
#include <cuda_bf16.h>
#include <cuda_fp16.h>
#include <math.h>
#include <stdint.h>

#define B_SZ  4
#define NSEQ  1024
#define DIMM  2048
#define KDIM  2048
#define NH    16
#define NKV   4
#define DH    128
#define MTOT  (B_SZ * NSEQ)

// ---------------- scratch (device globals: no allocation allowed) ----------
__device__ float g_Qh[B_SZ * NH  * NSEQ * DH];     // fp32 [b,h,n,d]
__device__ float g_Kh[B_SZ * NKV * NSEQ * DH];
__device__ float g_Vh[B_SZ * NKV * NSEQ * DH];
__device__ __nv_bfloat16 g_xhi[MTOT * KDIM], g_xlo[MTOT * KDIM];
__device__ __nv_bfloat16 g_Wch[3072 * KDIM], g_Wcl[3072 * KDIM];   // Wq|Wk|Wv ^T
__device__ __half g_WoF[2048 * KDIM];                              // Wo^T fp16
__device__ __half g_OhF[MTOT * DIMM], g_OlF[MTOT * DIMM];          // attn out fp16 hi/lo
__device__ __nv_bfloat16 g_Qbh[B_SZ * NH  * NSEQ * DH], g_Qbl[B_SZ * NH  * NSEQ * DH];
__device__ __nv_bfloat16 g_Kbh[B_SZ * NKV * NSEQ * DH], g_Kbl[B_SZ * NKV * NSEQ * DH];
__device__ __nv_bfloat16 g_Vbh[B_SZ * NKV * NSEQ * DH], g_Vbl[B_SZ * NKV * NSEQ * DH];
__device__ float g_cs[NSEQ * 64 * 2];              // rope cos/sin table

// ---------------- helpers ---------------------------------------------------
__device__ __forceinline__ uint32_t cvta_s(const void* p) {
    uint32_t a;
    asm("{ .reg .u64 t; cvta.to.shared.u64 t, %1; cvt.u32.u64 %0, t; }"
        : "=r"(a) : "l"(p));
    return a;
}
__device__ __forceinline__ void cp16(uint32_t dst, const void* src) {
    asm volatile("cp.async.cg.shared.global [%0], [%1], 16;"
                 :: "r"(dst), "l"(src) : "memory");
}
__device__ __forceinline__ void ldsm4(uint32_t* r, uint32_t addr) {
    asm volatile("ldmatrix.sync.aligned.m8n8.x4.shared.b16 {%0,%1,%2,%3}, [%4];"
                 : "=r"(r[0]), "=r"(r[1]), "=r"(r[2]), "=r"(r[3]) : "r"(addr));
}
__device__ __forceinline__ void ldsm4t(uint32_t* r, uint32_t addr) {
    asm volatile("ldmatrix.sync.aligned.m8n8.x4.trans.shared.b16 {%0,%1,%2,%3}, [%4];"
                 : "=r"(r[0]), "=r"(r[1]), "=r"(r[2]), "=r"(r[3]) : "r"(addr));
}
__device__ __forceinline__ void mma16816(float* d, const uint32_t* a,
                                         const uint32_t* b) {
    asm volatile(
        "mma.sync.aligned.m16n8k16.row.col.f32.bf16.bf16.f32 "
        "{%0,%1,%2,%3}, {%4,%5,%6,%7}, {%8,%9}, {%0,%1,%2,%3};"
        : "+f"(d[0]), "+f"(d[1]), "+f"(d[2]), "+f"(d[3])
        : "r"(a[0]), "r"(a[1]), "r"(a[2]), "r"(a[3]), "r"(b[0]), "r"(b[1]));
}
__device__ __forceinline__ void mma16816h(float* d, const uint32_t* a,
                                          const uint32_t* b) {
    asm volatile(
        "mma.sync.aligned.m16n8k16.row.col.f32.f16.f16.f32 "
        "{%0,%1,%2,%3}, {%4,%5,%6,%7}, {%8,%9}, {%0,%1,%2,%3};"
        : "+f"(d[0]), "+f"(d[1]), "+f"(d[2]), "+f"(d[3])
        : "r"(a[0]), "r"(a[1]), "r"(a[2]), "r"(a[3]), "r"(b[0]), "r"(b[1]));
}
__device__ __forceinline__ void pack_hl(float v0, float v1,
                                        uint32_t& hi2, uint32_t& lo2) {
    __nv_bfloat16 h0 = __float2bfloat16(v0), h1 = __float2bfloat16(v1);
    __nv_bfloat162 hp(h0, h1);
    hi2 = *reinterpret_cast<uint32_t*>(&hp);
    __nv_bfloat162 lp(__float2bfloat16(v0 - __bfloat162float(h0)),
                      __float2bfloat16(v1 - __bfloat162float(h1)));
    lo2 = *reinterpret_cast<uint32_t*>(&lp);
}

// ---------------- prep kernels ---------------------------------------------
__global__ void rope_table(float* __restrict__ cs)
{
    int idx = blockIdx.x * blockDim.x + threadIdx.x;
    if (idx >= NSEQ * 64) return;
    int i = idx & 63, n = idx >> 6;
    double invf = exp(-(double)i * 0.14391156831212787);
    double s, c;
    sincos((double)n * invf, &s, &c);
    cs[idx * 2]     = (float)c;
    cs[idx * 2 + 1] = (float)s;
}

__global__ __launch_bounds__(256) void prep_split(const float* __restrict__ x,
                                                  __nv_bfloat16* __restrict__ hi,
                                                  __nv_bfloat16* __restrict__ lo,
                                                  int n4)
{
    int idx = blockIdx.x * blockDim.x + threadIdx.x;
    if (idx >= n4) return;
    float4 v = ((const float4*)x)[idx];
    __nv_bfloat16 h0 = __float2bfloat16(v.x), h1 = __float2bfloat16(v.y);
    __nv_bfloat16 h2 = __float2bfloat16(v.z), h3 = __float2bfloat16(v.w);
    __nv_bfloat162* hp = (__nv_bfloat162*)hi;
    __nv_bfloat162* lp = (__nv_bfloat162*)lo;
    hp[2*idx]   = __nv_bfloat162(h0, h1);
    hp[2*idx+1] = __nv_bfloat162(h2, h3);
    lp[2*idx]   = __nv_bfloat162(__float2bfloat16(v.x - __bfloat162float(h0)),
                                 __float2bfloat16(v.y - __bfloat162float(h1)));
    lp[2*idx+1] = __nv_bfloat162(__float2bfloat16(v.z - __bfloat162float(h2)),
                                 __float2bfloat16(v.w - __bfloat162float(h3)));
}

// weights -> W^T[n][k]; Q/K/V bf16 hi/lo into combined buffer; Wo single fp16.
__global__ __launch_bounds__(256) void wtrans_all(
    const float* __restrict__ Wq, const float* __restrict__ Wk,
    const float* __restrict__ Wv, const float* __restrict__ Wo,
    __nv_bfloat16* ch, __nv_bfloat16* cl, __half* wof)
{
    const float* W; __nv_bfloat16 *th, *tl; int N;
    switch (blockIdx.z) {
        case 0:  W = Wq; th = ch;               tl = cl;               N = 2048; break;
        case 1:  W = Wk; th = ch + 2048 * KDIM; tl = cl + 2048 * KDIM; N = 512;  break;
        case 2:  W = Wv; th = ch + 2560 * KDIM; tl = cl + 2560 * KDIM; N = 512;  break;
        default: W = Wo; th = nullptr;          tl = nullptr;          N = 2048; break;
    }
    int n0 = blockIdx.x * 32, k0 = blockIdx.y * 32;
    if (n0 >= N) return;
    __shared__ float t[32][33];
    int tx = threadIdx.x & 31, ty = threadIdx.x >> 5;
#pragma unroll
    for (int j = 0; j < 32; j += 8)
        t[ty + j][tx] = W[(size_t)(k0 + ty + j) * N + n0 + tx];
    __syncthreads();
#pragma unroll
    for (int j = 0; j < 32; j += 8) {
        float v = t[tx][ty + j];
        size_t o = (size_t)(n0 + ty + j) * KDIM + k0 + tx;
        if (blockIdx.z == 3) {
            wof[o] = __float2half(v);
        } else {
            __nv_bfloat16 h = __float2bfloat16(v);
            th[o] = h;
            tl[o] = __float2bfloat16(v - __bfloat162float(h));
        }
    }
}

// ---------------- post_all: ropeQ + ropeK + V split (one launch) -----------
__global__ __launch_bounds__(256) void post_all(
    const float* __restrict__ Qh, const float* __restrict__ Kh,
    const float* __restrict__ Vh, const float* __restrict__ cs,
    __nv_bfloat16* __restrict__ Qbh, __nv_bfloat16* __restrict__ Qbl,
    __nv_bfloat16* __restrict__ Kbh, __nv_bfloat16* __restrict__ Kbl,
    __nv_bfloat16* __restrict__ Vbh, __nv_bfloat16* __restrict__ Vbl)
{
    const int blk = blockIdx.x, tid = threadIdx.x;
    if (blk < 20480) {
        const float* src; __nv_bfloat16 *hi, *lo; int idx;
        if (blk < 16384) { src = Qh; hi = Qbh; lo = Qbl; idx = blk * 256 + tid; }
        else             { src = Kh; hi = Kbh; lo = Kbl; idx = (blk - 16384) * 256 + tid; }
        int i   = idx & 63;
        int n   = (idx >> 6) & 1023;
        int bhd = idx >> 16;
        float2 v = ((const float2*)cs)[n * 64 + i];
        size_t o0 = (size_t)bhd * (NSEQ * DH) + n * DH + i;
        float t1 = src[o0], t2 = src[o0 + 64];
        float r0 = t1 * v.x - t2 * v.y;
        float r1 = t2 * v.x + t1 * v.y;
        __nv_bfloat16 b0 = __float2bfloat16(r0);
        __nv_bfloat16 b1 = __float2bfloat16(r1);
        hi[o0]      = b0; lo[o0]      = __float2bfloat16(r0 - __bfloat162float(b0));
        hi[o0 + 64] = b1; lo[o0 + 64] = __float2bfloat16(r1 - __bfloat162float(b1));
        return;
    }
    int idx = (blk - 20480) * 256 + tid;
    float4 v = ((const float4*)Vh)[idx];
    __nv_bfloat16 h0 = __float2bfloat16(v.x), h1 = __float2bfloat16(v.y);
    __nv_bfloat16 h2 = __float2bfloat16(v.z), h3 = __float2bfloat16(v.w);
    __nv_bfloat162* hp = (__nv_bfloat162*)Vbh;
    __nv_bfloat162* lp = (__nv_bfloat162*)Vbl;
    hp[2*idx]   = __nv_bfloat162(h0, h1);
    hp[2*idx+1] = __nv_bfloat162(h2, h3);
    lp[2*idx]   = __nv_bfloat162(__float2bfloat16(v.x - __bfloat162float(h0)),
                                 __float2bfloat16(v.y - __bfloat162float(h1)));
    lp[2*idx+1] = __nv_bfloat162(__float2bfloat16(v.z - __bfloat162float(h2)),
                                 __float2bfloat16(v.w - __bfloat162float(h3)));
}

// ---------------- QKV GEMM: bf16 3-pass, 3-stage cp.async (R13-proven) -----
__global__ __launch_bounds__(256)
void gemm_mma(const __nv_bfloat16* __restrict__ Ahi, const __nv_bfloat16* __restrict__ Alo,
              const __nv_bfloat16* __restrict__ Bhi, const __nv_bfloat16* __restrict__ Blo,
              float* __restrict__ Cq, float* __restrict__ Ck, float* __restrict__ Cv)
{
    extern __shared__ __align__(16) char smem[];
    const uint32_t sb0 = cvta_s(smem);

    const int tid  = threadIdx.x;
    const int wid  = tid >> 5, lane = tid & 31;
    const int wm   = wid & 3,  wn   = wid >> 2;
    const int am   = wm * 32,  bn0  = wn * 64;
    const int bm   = blockIdx.y * 128, bn = blockIdx.x * 128;

    const __nv_bfloat16* srcs[4] = { Ahi + (size_t)bm * KDIM, Alo + (size_t)bm * KDIM,
                                     Bhi + (size_t)bn * KDIM, Blo + (size_t)bn * KDIM };

    const int lr[4] = { (tid + 0)   >> 3, (tid + 256) >> 3,
                        (tid + 512) >> 3, (tid + 768) >> 3 };
    const int lc[4] = { (tid + 0)   & 7,  (tid + 256) & 7,
                        (tid + 512) & 7,  (tid + 768) & 7 };

    float acc[2][8][4];
#pragma unroll
    for (int mi = 0; mi < 2; mi++)
#pragma unroll
        for (int ni = 0; ni < 8; ni++)
#pragma unroll
            for (int c = 0; c < 4; c++) acc[mi][ni][c] = 0.f;

    const int NT = KDIM / 64;

    auto load_stage = [&](int s, int kt) {
        uint32_t sb = sb0 + s * 65536;
#pragma unroll
        for (int tt = 0; tt < 4; tt++) {
            const __nv_bfloat16* src = srcs[tt];
#pragma unroll
            for (int a = 0; a < 4; a++) {
                int r = lr[a], c4 = lc[a];
                uint32_t dst = sb + tt * 16384 + r * 128 + ((c4 ^ (r & 7)) << 4);
                cp16(dst, src + (size_t)r * KDIM + kt + c4 * 8);
            }
        }
        asm volatile("cp.async.commit_group;" ::: "memory");
    };

    load_stage(0, 0);
    load_stage(1, 64);

    int buf = 0;
    for (int it = 0; it < NT; ++it) {
        if (it + 1 < NT) {
            asm volatile("cp.async.wait_group 1;" ::: "memory");
        } else {
            asm volatile("cp.async.wait_group 0;" ::: "memory");
        }
        __syncthreads();
        if (it + 2 < NT) {
            int nb = buf + 2; if (nb >= 3) nb -= 3;
            load_stage(nb, (it + 2) * 64);
        }

        const uint32_t sb = sb0 + buf * 65536;
#pragma unroll
        for (int ks = 0; ks < 4; ks++) {
            uint32_t ah[2][4], al[2][4], bh[8][2], bl[8][2];
#pragma unroll
            for (int mi = 0; mi < 2; mi++) {
                int r  = am + mi * 16 + (lane & 15);
                int c4 = ks * 2 + (lane >> 4);
                uint32_t off = r * 128 + ((c4 ^ (r & 7)) << 4);
                ldsm4(ah[mi], sb + off);
                ldsm4(al[mi], sb + 16384 + off);
            }
#pragma unroll
            for (int nb2 = 0; nb2 < 4; nb2++) {
                int r  = bn0 + nb2 * 16 + (lane & 15);
                int c4 = ks * 2 + (lane >> 4);
                uint32_t off = r * 128 + ((c4 ^ (r & 7)) << 4);
                uint32_t t[4];
                ldsm4(t, sb + 32768 + off);
                bh[nb2*2][0]   = t[0]; bh[nb2*2][1]   = t[2];
                bh[nb2*2+1][0] = t[1]; bh[nb2*2+1][1] = t[3];
                ldsm4(t, sb + 49152 + off);
                bl[nb2*2][0]   = t[0]; bl[nb2*2][1]   = t[2];
                bl[nb2*2+1][0] = t[1]; bl[nb2*2+1][1] = t[3];
            }
#pragma unroll
            for (int mi = 0; mi < 2; mi++)
#pragma unroll
                for (int ni = 0; ni < 8; ni++) mma16816(acc[mi][ni], ah[mi], bh[ni]);
#pragma unroll
            for (int mi = 0; mi < 2; mi++)
#pragma unroll
                for (int ni = 0; ni < 8; ni++) mma16816(acc[mi][ni], al[mi], bh[ni]);
#pragma unroll
            for (int mi = 0; mi < 2; mi++)
#pragma unroll
                for (int ni = 0; ni < 8; ni++) mma16816(acc[mi][ni], ah[mi], bl[ni]);
        }
        if (++buf == 3) buf = 0;
    }

    // epilogue: route to Q/K/V head layout
    float* base; int h, Hout;
    if (bn < 2048)      { base = Cq; h = bn >> 7;          Hout = NH;  }
    else if (bn < 2560) { base = Ck; h = (bn - 2048) >> 7; Hout = NKV; }
    else                { base = Cv; h = (bn - 2560) >> 7; Hout = NKV; }
    const int g = lane >> 2, tig = lane & 3;
#pragma unroll
    for (int mi = 0; mi < 2; mi++) {
#pragma unroll
        for (int ni = 0; ni < 8; ni++) {
            int d   = bn0 + ni * 8 + tig * 2;
            int r0  = bm + am + mi * 16 + g;
            int r1  = r0 + 8;
            int b0 = r0 >> 10, n0 = r0 & 1023;
            int b1 = r1 >> 10, n1 = r1 & 1023;
            float* p0 = base + (((size_t)(b0 * Hout + h)) * NSEQ + n0) * DH + d;
            float* p1 = base + (((size_t)(b1 * Hout + h)) * NSEQ + n1) * DH + d;
            *(float2*)p0 = make_float2(acc[mi][ni][0], acc[mi][ni][1]);
            *(float2*)p1 = make_float2(acc[mi][ni][2], acc[mi][ni][3]);
        }
    }
}

// ---------------- O-projection GEMM: fp16 2-pass, 3-stage cp.async ---------
// A = OhF + OlF (fp16 split), B = WoF (single fp16). 32 mma/ks vs 48.
__global__ __launch_bounds__(256)
void gemm_o2(const __half* __restrict__ Ahi, const __half* __restrict__ Alo,
             const __half* __restrict__ B, float* __restrict__ C)
{
    extern __shared__ __align__(16) char smem[];
    const uint32_t sb0 = cvta_s(smem);

    const int tid  = threadIdx.x;
    const int wid  = tid >> 5, lane = tid & 31;
    const int wm   = wid & 3,  wn   = wid >> 2;
    const int am   = wm * 32,  bn0  = wn * 64;
    const int bm   = blockIdx.y * 128, bn = blockIdx.x * 128;

    const __half* srcs[3] = { Ahi + (size_t)bm * KDIM, Alo + (size_t)bm * KDIM,
                              B   + (size_t)bn * KDIM };

    const int lr[4] = { (tid + 0)   >> 3, (tid + 256) >> 3,
                        (tid + 512) >> 3, (tid + 768) >> 3 };
    const int lc[4] = { (tid + 0)   & 7,  (tid + 256) & 7,
                        (tid + 512) & 7,  (tid + 768) & 7 };

    float acc[2][8][4];
#pragma unroll
    for (int mi = 0; mi < 2; mi++)
#pragma unroll
        for (int ni = 0; ni < 8; ni++)
#pragma unroll
            for (int c = 0; c < 4; c++) acc[mi][ni][c] = 0.f;

    const int NT = KDIM / 64;

    auto load_stage = [&](int s, int kt) {
        uint32_t sb = sb0 + s * 49152;
#pragma unroll
        for (int tt = 0; tt < 3; tt++) {
            const __half* src = srcs[tt];
#pragma unroll
            for (int a = 0; a < 4; a++) {
                int r = lr[a], c4 = lc[a];
                uint32_t dst = sb + tt * 16384 + r * 128 + ((c4 ^ (r & 7)) << 4);
                cp16(dst, src + (size_t)r * KDIM + kt + c4 * 8);
            }
        }
        asm volatile("cp.async.commit_group;" ::: "memory");
    };

    load_stage(0, 0);
    load_stage(1, 64);

    int buf = 0;
    for (int it = 0; it < NT; ++it) {
        if (it + 1 < NT) {
            asm volatile("cp.async.wait_group 1;" ::: "memory");
        } else {
            asm volatile("cp.async.wait_group 0;" ::: "memory");
        }
        __syncthreads();
        if (it + 2 < NT) {
            int nb = buf + 2; if (nb >= 3) nb -= 3;
            load_stage(nb, (it + 2) * 64);
        }

        const uint32_t sb = sb0 + buf * 49152;
#pragma unroll
        for (int ks = 0; ks < 4; ks++) {
            uint32_t ah[2][4], al[2][4], bf[8][2];
#pragma unroll
            for (int mi = 0; mi < 2; mi++) {
                int r  = am + mi * 16 + (lane & 15);
                int c4 = ks * 2 + (lane >> 4);
                uint32_t off = r * 128 + ((c4 ^ (r & 7)) << 4);
                ldsm4(ah[mi], sb + off);
                ldsm4(al[mi], sb + 16384 + off);
            }
#pragma unroll
            for (int nb2 = 0; nb2 < 4; nb2++) {
                int r  = bn0 + nb2 * 16 + (lane & 15);
                int c4 = ks * 2 + (lane >> 4);
                uint32_t off = r * 128 + ((c4 ^ (r & 7)) << 4);
                uint32_t t[4];
                ldsm4(t, sb + 32768 + off);
                bf[nb2*2][0]   = t[0]; bf[nb2*2][1]   = t[2];
                bf[nb2*2+1][0] = t[1]; bf[nb2*2+1][1] = t[3];
            }
#pragma unroll
            for (int mi = 0; mi < 2; mi++)
#pragma unroll
                for (int ni = 0; ni < 8; ni++) mma16816h(acc[mi][ni], ah[mi], bf[ni]);
#pragma unroll
            for (int mi = 0; mi < 2; mi++)
#pragma unroll
                for (int ni = 0; ni < 8; ni++) mma16816h(acc[mi][ni], al[mi], bf[ni]);
        }
        if (++buf == 3) buf = 0;
    }

    const int g = lane >> 2, tig = lane & 3;
#pragma unroll
    for (int mi = 0; mi < 2; mi++) {
#pragma unroll
        for (int ni = 0; ni < 8; ni++) {
            int d  = bn0 + ni * 8 + tig * 2;
            int r0 = bm + am + mi * 16 + g;
            int r1 = r0 + 8;
            float* p0 = C + (size_t)r0 * DIMM + bn + d;
            float* p1 = C + (size_t)r1 * DIMM + bn + d;
            *(float2*)p0 = make_float2(acc[mi][ni][0], acc[mi][ni][1]);
            *(float2*)p1 = make_float2(acc[mi][ni][2], acc[mi][ni][3]);
        }
    }
}

// ---------------- tensor-core causal flash attention, P in registers -------
// q-tile 128 x kv-tile 64, 8 warps. Epilogue writes fp16 hi/lo O.
__global__ __launch_bounds__(256)
void flash_tc(const __nv_bfloat16* __restrict__ Qh_, const __nv_bfloat16* __restrict__ Ql_,
              const __nv_bfloat16* __restrict__ Kh_, const __nv_bfloat16* __restrict__ Kl_,
              const __nv_bfloat16* __restrict__ Vh_, const __nv_bfloat16* __restrict__ Vl_,
              const float* __restrict__ hsc,
              __half* __restrict__ OhF, __half* __restrict__ OlF)
{
    extern __shared__ __align__(16) char smc[];
    const uint32_t smb = cvta_s(smc);
    const int tid = threadIdx.x, wid = tid >> 5, lane = tid & 31;
    const int qb = 7 - blockIdx.x;
    const int bh = blockIdx.y, b = bh >> 4, h = bh & 15, kvh = h >> 2;
    const int m0 = wid * 16;
    const int g = lane >> 2, tig = lane & 3;
    const float scale = 0.08838834764831845f;

    const __nv_bfloat16* Qhg = Qh_ + ((size_t)(b * NH + h) * NSEQ + qb * 128) * DH;
    const __nv_bfloat16* Qlg = Ql_ + ((size_t)(b * NH + h) * NSEQ + qb * 128) * DH;
    const size_t kvb = (size_t)(b * NKV + kvh) * NSEQ * DH;

#pragma unroll
    for (int t = 0; t < 8; t++) {
        int e = tid + t * 256, r = e >> 4, c4 = e & 15;
        uint32_t off = r * 256 + ((c4 ^ (r & 7)) << 4);
        cp16(smb + off,         Qhg + r * DH + c4 * 8);
        cp16(smb + 32768 + off, Qlg + r * DH + c4 * 8);
    }
    auto ldkv = [&](int s, int kb) {
        const __nv_bfloat16* kh = Kh_ + kvb + (size_t)kb * 64 * DH;
        const __nv_bfloat16* kl = Kl_ + kvb + (size_t)kb * 64 * DH;
        const __nv_bfloat16* vh = Vh_ + kvb + (size_t)kb * 64 * DH;
        const __nv_bfloat16* vl = Vl_ + kvb + (size_t)kb * 64 * DH;
        uint32_t kd = smb + 65536  + s * 32768;
        uint32_t vd = smb + 131072 + s * 32768;
#pragma unroll
        for (int t = 0; t < 4; t++) {
            int e = tid + t * 256, r = e >> 4, c4 = e & 15;
            uint32_t off = r * 256 + ((c4 ^ (r & 7)) << 4);
            int go = r * DH + c4 * 8;
            cp16(kd + off,         kh + go);
            cp16(kd + 16384 + off, kl + go);
            cp16(vd + off,         vh + go);
            cp16(vd + 16384 + off, vl + go);
        }
        asm volatile("cp.async.commit_group;" ::: "memory");
    };
    ldkv(0, 0);

    float m_i[2] = {-1e30f, -1e30f}, l_i[2] = {0.f, 0.f};
    float o[16][4];
#pragma unroll
    for (int ni = 0; ni < 16; ni++)
#pragma unroll
        for (int c = 0; c < 4; c++) o[ni][c] = 0.f;

    const int kb_max = 2 * qb + 1;
    for (int kb = 0; kb <= kb_max; ++kb) {
        asm volatile("cp.async.wait_group 0;" ::: "memory");
        __syncthreads();
        if (kb < kb_max) ldkv((kb + 1) & 1, kb + 1);

        const uint32_t sK = smb + 65536  + (kb & 1) * 32768;
        const uint32_t sV = smb + 131072 + (kb & 1) * 32768;

        float sf[8][4];
#pragma unroll
        for (int ni = 0; ni < 8; ni++)
#pragma unroll
            for (int c = 0; c < 4; c++) sf[ni][c] = 0.f;

#pragma unroll
        for (int ks = 0; ks < 8; ks++) {
            uint32_t ah[4], al[4], bh2[8][2], bl2[8][2];
            {
                int r = m0 + (lane & 15), c4 = ks * 2 + (lane >> 4);
                uint32_t off = r * 256 + ((c4 ^ (r & 7)) << 4);
                ldsm4(ah, smb + off);
                ldsm4(al, smb + 32768 + off);
            }
#pragma unroll
            for (int nb = 0; nb < 4; nb++) {
                int r = nb * 16 + (lane & 15), c4 = ks * 2 + (lane >> 4);
                uint32_t off = r * 256 + ((c4 ^ (r & 7)) << 4);
                uint32_t t4r[4];
                ldsm4(t4r, sK + off);
                bh2[nb*2][0] = t4r[0]; bh2[nb*2][1] = t4r[2];
                bh2[nb*2+1][0] = t4r[1]; bh2[nb*2+1][1] = t4r[3];
                ldsm4(t4r, sK + 16384 + off);
                bl2[nb*2][0] = t4r[0]; bl2[nb*2][1] = t4r[2];
                bl2[nb*2+1][0] = t4r[1]; bl2[nb*2+1][1] = t4r[3];
            }
#pragma unroll
            for (int ni = 0; ni < 8; ni++) mma16816(sf[ni], ah, bh2[ni]);
#pragma unroll
            for (int ni = 0; ni < 8; ni++) mma16816(sf[ni], al, bh2[ni]);
#pragma unroll
            for (int ni = 0; ni < 8; ni++) mma16816(sf[ni], ah, bl2[ni]);
        }

        const bool near = (kb * 64 + 63) > (qb * 128 + m0);
#pragma unroll
        for (int rr = 0; rr < 2; rr++) {
            int row_g = qb * 128 + m0 + g + rr * 8;
            float mx = -1e30f;
#pragma unroll
            for (int ni = 0; ni < 8; ni++)
#pragma unroll
                for (int c = 0; c < 2; c++) {
                    float v = sf[ni][rr * 2 + c] * scale;
                    if (near && (kb * 64 + ni * 8 + tig * 2 + c) > row_g) v = -1e30f;
                    sf[ni][rr * 2 + c] = v;
                    mx = fmaxf(mx, v);
                }
            mx = fmaxf(mx, __shfl_xor_sync(0xffffffffu, mx, 1));
            mx = fmaxf(mx, __shfl_xor_sync(0xffffffffu, mx, 2));
            float mn    = fmaxf(m_i[rr], mx);
            float alpha = __expf(m_i[rr] - mn);
            m_i[rr] = mn;
            float rs = 0.f;
#pragma unroll
            for (int ni = 0; ni < 8; ni++)
#pragma unroll
                for (int c = 0; c < 2; c++) {
                    float p = __expf(sf[ni][rr * 2 + c] - mn);
                    sf[ni][rr * 2 + c] = p;
                    rs += p;
                }
            rs += __shfl_xor_sync(0xffffffffu, rs, 1);
            rs += __shfl_xor_sync(0xffffffffu, rs, 2);
            l_i[rr] = l_i[rr] * alpha + rs;
#pragma unroll
            for (int ni = 0; ni < 16; ni++) {
                o[ni][rr * 2]     *= alpha;
                o[ni][rr * 2 + 1] *= alpha;
            }
        }

#pragma unroll
        for (int ks = 0; ks < 4; ks++) {
            uint32_t ph[4], pl[4];
            pack_hl(sf[2*ks][0],   sf[2*ks][1],   ph[0], pl[0]);
            pack_hl(sf[2*ks][2],   sf[2*ks][3],   ph[1], pl[1]);
            pack_hl(sf[2*ks+1][0], sf[2*ks+1][1], ph[2], pl[2]);
            pack_hl(sf[2*ks+1][2], sf[2*ks+1][3], ph[3], pl[3]);
#pragma unroll
            for (int nb = 0; nb < 8; nb++) {
                int row = ks * 16 + (lane & 7) + ((lane & 16) >> 1);
                int ch  = nb * 2 + ((lane >> 3) & 1);
                uint32_t off = row * 256 + ((ch ^ (row & 7)) << 4);
                uint32_t t4r[4], bvh[2][2], bvl[2][2];
                ldsm4t(t4r, sV + off);
                bvh[0][0] = t4r[0]; bvh[0][1] = t4r[2];
                bvh[1][0] = t4r[1]; bvh[1][1] = t4r[3];
                ldsm4t(t4r, sV + 16384 + off);
                bvl[0][0] = t4r[0]; bvl[0][1] = t4r[2];
                bvl[1][0] = t4r[1]; bvl[1][1] = t4r[3];
                mma16816(o[nb*2],   ph, bvh[0]);
                mma16816(o[nb*2+1], ph, bvh[1]);
                mma16816(o[nb*2],   pl, bvh[0]);
                mma16816(o[nb*2+1], pl, bvh[1]);
                mma16816(o[nb*2],   ph, bvl[0]);
                mma16816(o[nb*2+1], ph, bvl[1]);
            }
        }
    }

    // epilogue: normalize, head-scale, write fp16 hi/lo O ([b,n,h*d] layout)
    const float hval = hsc[h];
#pragma unroll
    for (int rr = 0; rr < 2; rr++) {
        float inv = hval / l_i[rr];
        int n = qb * 128 + m0 + g + rr * 8;
        size_t base = ((size_t)(b * NSEQ + n)) * DIMM + h * DH;
#pragma unroll
        for (int ni = 0; ni < 16; ni++) {
            int col = ni * 8 + tig * 2;
            float v0 = o[ni][rr * 2] * inv, v1 = o[ni][rr * 2 + 1] * inv;
            __half h0 = __float2half(v0), h1 = __float2half(v1);
            *(__half2*)(OhF + base + col) = __halves2half2(h0, h1);
            *(__half2*)(OlF + base + col) =
                __halves2half2(__float2half(v0 - __half2float(h0)),
                               __float2half(v1 - __half2float(h1)));
        }
    }
}

// ---------------- launch ---------------------------------------------------
extern "C" void kernel_launch(void* const* d_in, const int* in_sizes, int n_in,
                              void* d_out, int out_size)
{
    const float* x   = (const float*)d_in[0];
    const float* Wq  = (const float*)d_in[1];
    const float* Wk  = (const float*)d_in[2];
    const float* Wv  = (const float*)d_in[3];
    const float* Wo  = (const float*)d_in[4];
    const float* hsc = (const float*)d_in[5];
    float* out = (float*)d_out;

    float *Qh, *Kh, *Vh, *cs;
    __nv_bfloat16 *xhi, *xlo, *Wch, *Wcl;
    __half *WoF, *OhF, *OlF;
    __nv_bfloat16 *Qbh, *Qbl, *Kbh, *Kbl, *Vbh, *Vbl;
    cudaGetSymbolAddress((void**)&Qh,  g_Qh);
    cudaGetSymbolAddress((void**)&Kh,  g_Kh);
    cudaGetSymbolAddress((void**)&Vh,  g_Vh);
    cudaGetSymbolAddress((void**)&cs,  g_cs);
    cudaGetSymbolAddress((void**)&xhi, g_xhi);  cudaGetSymbolAddress((void**)&xlo, g_xlo);
    cudaGetSymbolAddress((void**)&Wch, g_Wch);  cudaGetSymbolAddress((void**)&Wcl, g_Wcl);
    cudaGetSymbolAddress((void**)&WoF, g_WoF);
    cudaGetSymbolAddress((void**)&OhF, g_OhF);  cudaGetSymbolAddress((void**)&OlF, g_OlF);
    cudaGetSymbolAddress((void**)&Qbh, g_Qbh);  cudaGetSymbolAddress((void**)&Qbl, g_Qbl);
    cudaGetSymbolAddress((void**)&Kbh, g_Kbh);  cudaGetSymbolAddress((void**)&Kbl, g_Kbl);
    cudaGetSymbolAddress((void**)&Vbh, g_Vbh);  cudaGetSymbolAddress((void**)&Vbl, g_Vbl);

    // launches 1..3: prep
    rope_table<<<(NSEQ * 64 + 255) / 256, 256>>>(cs);
    prep_split<<<(MTOT * KDIM / 4 + 255) / 256, 256>>>(x, xhi, xlo, MTOT * KDIM / 4);
    wtrans_all<<<dim3(64, 64, 4), 256>>>(Wq, Wk, Wv, Wo, Wch, Wcl, WoF);

    // launch 4 (profiled slot): merged QKV projection (bf16 3-pass)
    const int gsm = 196608;     // 3 stages x 64KB
    cudaFuncSetAttribute(gemm_mma, cudaFuncAttributeMaxDynamicSharedMemorySize, gsm);
    gemm_mma<<<dim3(24, 32), 256, gsm>>>(xhi, xlo, Wch, Wcl, Qh, Kh, Vh);

    // launch 5: rope Q/K + V split
    post_all<<<22528, 256>>>(Qh, Kh, Vh, cs, Qbh, Qbl, Kbh, Kbl, Vbh, Vbl);

    // launch 6: tensor-core flash attention (writes fp16 hi/lo O)
    const int fsm = 196608;
    cudaFuncSetAttribute(flash_tc, cudaFuncAttributeMaxDynamicSharedMemorySize, fsm);
    flash_tc<<<dim3(8, B_SZ * NH), 256, fsm>>>(Qbh, Qbl, Kbh, Kbl, Vbh, Vbl,
                                               hsc, OhF, OlF);

    // launch 7: output projection (fp16 2-pass)
    const int osm = 147456;     // 3 stages x 48KB
    cudaFuncSetAttribute(gemm_o2, cudaFuncAttributeMaxDynamicSharedMemorySize, osm);
    gemm_o2<<<dim3(16, 32), 256, osm>>>(OhF, OlF, WoF, out);
}

// round 15
// speedup vs baseline: 1.2517x; 1.1490x over previous
#include <cuda_runtime.h>
#include <cuda_bf16.h>
#include <cuda_fp16.h>
#include <math.h>
#include <stdint.h>

#define B_SZ  4
#define NSEQ  1024
#define DIMM  2048
#define KDIM  2048
#define NH    16
#define NKV   4
#define DH    128
#define MTOT  (B_SZ * NSEQ)

// ---------------- scratch (device globals: no allocation allowed) ----------
__device__ float g_Qh[B_SZ * NH  * NSEQ * DH];     // fp32 [b,h,n,d]
__device__ float g_Kh[B_SZ * NKV * NSEQ * DH];
__device__ float g_Vh[B_SZ * NKV * NSEQ * DH];
__device__ __half g_xhF[MTOT * KDIM], g_xlF[MTOT * KDIM];          // x fp16 hi/lo
__device__ __half g_WcF[3072 * KDIM];                              // Wq|Wk|Wv ^T fp16
__device__ __half g_WoF[2048 * KDIM];                              // Wo^T fp16
__device__ __half g_OhF[MTOT * DIMM], g_OlF[MTOT * DIMM];          // attn out fp16 hi/lo
__device__ __nv_bfloat16 g_Qbh[B_SZ * NH  * NSEQ * DH], g_Qbl[B_SZ * NH  * NSEQ * DH];
__device__ __nv_bfloat16 g_Kbh[B_SZ * NKV * NSEQ * DH], g_Kbl[B_SZ * NKV * NSEQ * DH];
__device__ __nv_bfloat16 g_Vbh[B_SZ * NKV * NSEQ * DH], g_Vbl[B_SZ * NKV * NSEQ * DH];
__device__ float g_cs[NSEQ * 64 * 2];              // rope cos/sin table

// ---------------- helpers ---------------------------------------------------
__device__ __forceinline__ uint32_t cvta_s(const void* p) {
    uint32_t a;
    asm("{ .reg .u64 t; cvta.to.shared.u64 t, %1; cvt.u32.u64 %0, t; }"
        : "=r"(a) : "l"(p));
    return a;
}
__device__ __forceinline__ void cp16(uint32_t dst, const void* src) {
    asm volatile("cp.async.cg.shared.global [%0], [%1], 16;"
                 :: "r"(dst), "l"(src) : "memory");
}
__device__ __forceinline__ void ldsm4(uint32_t* r, uint32_t addr) {
    asm volatile("ldmatrix.sync.aligned.m8n8.x4.shared.b16 {%0,%1,%2,%3}, [%4];"
                 : "=r"(r[0]), "=r"(r[1]), "=r"(r[2]), "=r"(r[3]) : "r"(addr));
}
__device__ __forceinline__ void ldsm4t(uint32_t* r, uint32_t addr) {
    asm volatile("ldmatrix.sync.aligned.m8n8.x4.trans.shared.b16 {%0,%1,%2,%3}, [%4];"
                 : "=r"(r[0]), "=r"(r[1]), "=r"(r[2]), "=r"(r[3]) : "r"(addr));
}
__device__ __forceinline__ void mma16816(float* d, const uint32_t* a,
                                         const uint32_t* b) {
    asm volatile(
        "mma.sync.aligned.m16n8k16.row.col.f32.bf16.bf16.f32 "
        "{%0,%1,%2,%3}, {%4,%5,%6,%7}, {%8,%9}, {%0,%1,%2,%3};"
        : "+f"(d[0]), "+f"(d[1]), "+f"(d[2]), "+f"(d[3])
        : "r"(a[0]), "r"(a[1]), "r"(a[2]), "r"(a[3]), "r"(b[0]), "r"(b[1]));
}
__device__ __forceinline__ void mma16816h(float* d, const uint32_t* a,
                                          const uint32_t* b) {
    asm volatile(
        "mma.sync.aligned.m16n8k16.row.col.f32.f16.f16.f32 "
        "{%0,%1,%2,%3}, {%4,%5,%6,%7}, {%8,%9}, {%0,%1,%2,%3};"
        : "+f"(d[0]), "+f"(d[1]), "+f"(d[2]), "+f"(d[3])
        : "r"(a[0]), "r"(a[1]), "r"(a[2]), "r"(a[3]), "r"(b[0]), "r"(b[1]));
}
__device__ __forceinline__ void pack_hl(float v0, float v1,
                                        uint32_t& hi2, uint32_t& lo2) {
    __nv_bfloat16 h0 = __float2bfloat16(v0), h1 = __float2bfloat16(v1);
    __nv_bfloat162 hp(h0, h1);
    hi2 = *reinterpret_cast<uint32_t*>(&hp);
    __nv_bfloat162 lp(__float2bfloat16(v0 - __bfloat162float(h0)),
                      __float2bfloat16(v1 - __bfloat162float(h1)));
    lo2 = *reinterpret_cast<uint32_t*>(&lp);
}

// ---------------- prep kernels ---------------------------------------------
__global__ void rope_table(float* __restrict__ cs)
{
    int idx = blockIdx.x * blockDim.x + threadIdx.x;
    if (idx >= NSEQ * 64) return;
    int i = idx & 63, n = idx >> 6;
    double invf = exp(-(double)i * 0.14391156831212787);
    double s, c;
    sincos((double)n * invf, &s, &c);
    cs[idx * 2]     = (float)c;
    cs[idx * 2 + 1] = (float)s;
}

// x fp32 -> fp16 hi/lo split
__global__ __launch_bounds__(256) void prep_split_f16(const float* __restrict__ x,
                                                      __half* __restrict__ hi,
                                                      __half* __restrict__ lo,
                                                      int n4)
{
    int idx = blockIdx.x * blockDim.x + threadIdx.x;
    if (idx >= n4) return;
    float4 v = ((const float4*)x)[idx];
    __half h0 = __float2half(v.x), h1 = __float2half(v.y);
    __half h2 = __float2half(v.z), h3 = __float2half(v.w);
    __half2* hp = (__half2*)hi;
    __half2* lp = (__half2*)lo;
    hp[2*idx]   = __halves2half2(h0, h1);
    hp[2*idx+1] = __halves2half2(h2, h3);
    lp[2*idx]   = __halves2half2(__float2half(v.x - __half2float(h0)),
                                 __float2half(v.y - __half2float(h1)));
    lp[2*idx+1] = __halves2half2(__float2half(v.z - __half2float(h2)),
                                 __float2half(v.w - __half2float(h3)));
}

// all weights -> W^T[n][k] single fp16 (Q/K/V combined, Wo separate).
__global__ __launch_bounds__(256) void wtrans_all(
    const float* __restrict__ Wq, const float* __restrict__ Wk,
    const float* __restrict__ Wv, const float* __restrict__ Wo,
    __half* wc, __half* wof)
{
    const float* W; __half* th; int N;
    switch (blockIdx.z) {
        case 0:  W = Wq; th = wc;               N = 2048; break;
        case 1:  W = Wk; th = wc + 2048 * KDIM; N = 512;  break;
        case 2:  W = Wv; th = wc + 2560 * KDIM; N = 512;  break;
        default: W = Wo; th = wof;              N = 2048; break;
    }
    int n0 = blockIdx.x * 32, k0 = blockIdx.y * 32;
    if (n0 >= N) return;
    __shared__ float t[32][33];
    int tx = threadIdx.x & 31, ty = threadIdx.x >> 5;
#pragma unroll
    for (int j = 0; j < 32; j += 8)
        t[ty + j][tx] = W[(size_t)(k0 + ty + j) * N + n0 + tx];
    __syncthreads();
#pragma unroll
    for (int j = 0; j < 32; j += 8)
        th[(size_t)(n0 + ty + j) * KDIM + k0 + tx] = __float2half(t[tx][ty + j]);
}

// ---------------- post_all: ropeQ + ropeK + V split (bf16 hi/lo) -----------
__global__ __launch_bounds__(256) void post_all(
    const float* __restrict__ Qh, const float* __restrict__ Kh,
    const float* __restrict__ Vh, const float* __restrict__ cs,
    __nv_bfloat16* __restrict__ Qbh, __nv_bfloat16* __restrict__ Qbl,
    __nv_bfloat16* __restrict__ Kbh, __nv_bfloat16* __restrict__ Kbl,
    __nv_bfloat16* __restrict__ Vbh, __nv_bfloat16* __restrict__ Vbl)
{
    const int blk = blockIdx.x, tid = threadIdx.x;
    if (blk < 20480) {
        const float* src; __nv_bfloat16 *hi, *lo; int idx;
        if (blk < 16384) { src = Qh; hi = Qbh; lo = Qbl; idx = blk * 256 + tid; }
        else             { src = Kh; hi = Kbh; lo = Kbl; idx = (blk - 16384) * 256 + tid; }
        int i   = idx & 63;
        int n   = (idx >> 6) & 1023;
        int bhd = idx >> 16;
        float2 v = ((const float2*)cs)[n * 64 + i];
        size_t o0 = (size_t)bhd * (NSEQ * DH) + n * DH + i;
        float t1 = src[o0], t2 = src[o0 + 64];
        float r0 = t1 * v.x - t2 * v.y;
        float r1 = t2 * v.x + t1 * v.y;
        __nv_bfloat16 b0 = __float2bfloat16(r0);
        __nv_bfloat16 b1 = __float2bfloat16(r1);
        hi[o0]      = b0; lo[o0]      = __float2bfloat16(r0 - __bfloat162float(b0));
        hi[o0 + 64] = b1; lo[o0 + 64] = __float2bfloat16(r1 - __bfloat162float(b1));
        return;
    }
    int idx = (blk - 20480) * 256 + tid;
    float4 v = ((const float4*)Vh)[idx];
    __nv_bfloat16 h0 = __float2bfloat16(v.x), h1 = __float2bfloat16(v.y);
    __nv_bfloat16 h2 = __float2bfloat16(v.z), h3 = __float2bfloat16(v.w);
    __nv_bfloat162* hp = (__nv_bfloat162*)Vbh;
    __nv_bfloat162* lp = (__nv_bfloat162*)Vbl;
    hp[2*idx]   = __nv_bfloat162(h0, h1);
    hp[2*idx+1] = __nv_bfloat162(h2, h3);
    lp[2*idx]   = __nv_bfloat162(__float2bfloat16(v.x - __bfloat162float(h0)),
                                 __float2bfloat16(v.y - __bfloat162float(h1)));
    lp[2*idx+1] = __nv_bfloat162(__float2bfloat16(v.z - __bfloat162float(h2)),
                                 __float2bfloat16(v.w - __bfloat162float(h3)));
}

// ---------------- fp16 2-pass GEMM: 3-stage cp.async, 48KB/stage -----------
// C = (Ahi + Alo) @ B^T ; A fp16 split, B single fp16 [N][K].
// MODE 1: QKV combined (route to Q/K/V head layout); MODE 0: plain [M][DIMM].
template <int MODE>
__global__ __launch_bounds__(256)
void gemm_f16(const __half* __restrict__ Ahi, const __half* __restrict__ Alo,
              const __half* __restrict__ B,
              float* __restrict__ Cq, float* __restrict__ Ck, float* __restrict__ Cv)
{
    extern __shared__ __align__(16) char smem[];
    const uint32_t sb0 = cvta_s(smem);

    const int tid  = threadIdx.x;
    const int wid  = tid >> 5, lane = tid & 31;
    const int wm   = wid & 3,  wn   = wid >> 2;
    const int am   = wm * 32,  bn0  = wn * 64;
    const int bm   = blockIdx.y * 128, bn = blockIdx.x * 128;

    const __half* srcs[3] = { Ahi + (size_t)bm * KDIM, Alo + (size_t)bm * KDIM,
                              B   + (size_t)bn * KDIM };

    const int lr[4] = { (tid + 0)   >> 3, (tid + 256) >> 3,
                        (tid + 512) >> 3, (tid + 768) >> 3 };
    const int lc[4] = { (tid + 0)   & 7,  (tid + 256) & 7,
                        (tid + 512) & 7,  (tid + 768) & 7 };

    float acc[2][8][4];
#pragma unroll
    for (int mi = 0; mi < 2; mi++)
#pragma unroll
        for (int ni = 0; ni < 8; ni++)
#pragma unroll
            for (int c = 0; c < 4; c++) acc[mi][ni][c] = 0.f;

    const int NT = KDIM / 64;

    auto load_stage = [&](int s, int kt) {
        uint32_t sb = sb0 + s * 49152;
#pragma unroll
        for (int tt = 0; tt < 3; tt++) {
            const __half* src = srcs[tt];
#pragma unroll
            for (int a = 0; a < 4; a++) {
                int r = lr[a], c4 = lc[a];
                uint32_t dst = sb + tt * 16384 + r * 128 + ((c4 ^ (r & 7)) << 4);
                cp16(dst, src + (size_t)r * KDIM + kt + c4 * 8);
            }
        }
        asm volatile("cp.async.commit_group;" ::: "memory");
    };

    load_stage(0, 0);
    load_stage(1, 64);

    int buf = 0;
    for (int it = 0; it < NT; ++it) {
        if (it + 1 < NT) {
            asm volatile("cp.async.wait_group 1;" ::: "memory");
        } else {
            asm volatile("cp.async.wait_group 0;" ::: "memory");
        }
        __syncthreads();
        if (it + 2 < NT) {
            int nb = buf + 2; if (nb >= 3) nb -= 3;
            load_stage(nb, (it + 2) * 64);
        }

        const uint32_t sb = sb0 + buf * 49152;
#pragma unroll
        for (int ks = 0; ks < 4; ks++) {
            uint32_t ah[2][4], al[2][4], bf[8][2];
#pragma unroll
            for (int mi = 0; mi < 2; mi++) {
                int r  = am + mi * 16 + (lane & 15);
                int c4 = ks * 2 + (lane >> 4);
                uint32_t off = r * 128 + ((c4 ^ (r & 7)) << 4);
                ldsm4(ah[mi], sb + off);
                ldsm4(al[mi], sb + 16384 + off);
            }
#pragma unroll
            for (int nb2 = 0; nb2 < 4; nb2++) {
                int r  = bn0 + nb2 * 16 + (lane & 15);
                int c4 = ks * 2 + (lane >> 4);
                uint32_t off = r * 128 + ((c4 ^ (r & 7)) << 4);
                uint32_t t[4];
                ldsm4(t, sb + 32768 + off);
                bf[nb2*2][0]   = t[0]; bf[nb2*2][1]   = t[2];
                bf[nb2*2+1][0] = t[1]; bf[nb2*2+1][1] = t[3];
            }
#pragma unroll
            for (int mi = 0; mi < 2; mi++)
#pragma unroll
                for (int ni = 0; ni < 8; ni++) mma16816h(acc[mi][ni], ah[mi], bf[ni]);
#pragma unroll
            for (int mi = 0; mi < 2; mi++)
#pragma unroll
                for (int ni = 0; ni < 8; ni++) mma16816h(acc[mi][ni], al[mi], bf[ni]);
        }
        if (++buf == 3) buf = 0;
    }

    // epilogue
    float* base; int h = 0, Hout = 0;
    if (MODE == 1) {
        if (bn < 2048)      { base = Cq; h = bn >> 7;          Hout = NH;  }
        else if (bn < 2560) { base = Ck; h = (bn - 2048) >> 7; Hout = NKV; }
        else                { base = Cv; h = (bn - 2560) >> 7; Hout = NKV; }
    } else {
        base = Cq;
    }
    const int g = lane >> 2, tig = lane & 3;
#pragma unroll
    for (int mi = 0; mi < 2; mi++) {
#pragma unroll
        for (int ni = 0; ni < 8; ni++) {
            int d   = bn0 + ni * 8 + tig * 2;
            int r0  = bm + am + mi * 16 + g;
            int r1  = r0 + 8;
            float* p0;
            float* p1;
            if (MODE == 1) {
                int b0 = r0 >> 10, n0 = r0 & 1023;
                int b1 = r1 >> 10, n1 = r1 & 1023;
                p0 = base + (((size_t)(b0 * Hout + h)) * NSEQ + n0) * DH + d;
                p1 = base + (((size_t)(b1 * Hout + h)) * NSEQ + n1) * DH + d;
            } else {
                p0 = base + (size_t)r0 * DIMM + bn + d;
                p1 = base + (size_t)r1 * DIMM + bn + d;
            }
            *(float2*)p0 = make_float2(acc[mi][ni][0], acc[mi][ni][1]);
            *(float2*)p1 = make_float2(acc[mi][ni][2], acc[mi][ni][3]);
        }
    }
}

// ---------------- tensor-core causal flash attention (bf16 3-pass) ---------
// q-tile 128 x kv-tile 64, 8 warps, P in registers; writes fp16 hi/lo O.
__global__ __launch_bounds__(256)
void flash_tc(const __nv_bfloat16* __restrict__ Qh_, const __nv_bfloat16* __restrict__ Ql_,
              const __nv_bfloat16* __restrict__ Kh_, const __nv_bfloat16* __restrict__ Kl_,
              const __nv_bfloat16* __restrict__ Vh_, const __nv_bfloat16* __restrict__ Vl_,
              const float* __restrict__ hsc,
              __half* __restrict__ OhF, __half* __restrict__ OlF)
{
    extern __shared__ __align__(16) char smc[];
    const uint32_t smb = cvta_s(smc);
    const int tid = threadIdx.x, wid = tid >> 5, lane = tid & 31;
    const int qb = 7 - blockIdx.x;
    const int bh = blockIdx.y, b = bh >> 4, h = bh & 15, kvh = h >> 2;
    const int m0 = wid * 16;
    const int g = lane >> 2, tig = lane & 3;
    const float scale = 0.08838834764831845f;

    const __nv_bfloat16* Qhg = Qh_ + ((size_t)(b * NH + h) * NSEQ + qb * 128) * DH;
    const __nv_bfloat16* Qlg = Ql_ + ((size_t)(b * NH + h) * NSEQ + qb * 128) * DH;
    const size_t kvb = (size_t)(b * NKV + kvh) * NSEQ * DH;

#pragma unroll
    for (int t = 0; t < 8; t++) {
        int e = tid + t * 256, r = e >> 4, c4 = e & 15;
        uint32_t off = r * 256 + ((c4 ^ (r & 7)) << 4);
        cp16(smb + off,         Qhg + r * DH + c4 * 8);
        cp16(smb + 32768 + off, Qlg + r * DH + c4 * 8);
    }
    auto ldkv = [&](int s, int kb) {
        const __nv_bfloat16* kh = Kh_ + kvb + (size_t)kb * 64 * DH;
        const __nv_bfloat16* kl = Kl_ + kvb + (size_t)kb * 64 * DH;
        const __nv_bfloat16* vh = Vh_ + kvb + (size_t)kb * 64 * DH;
        const __nv_bfloat16* vl = Vl_ + kvb + (size_t)kb * 64 * DH;
        uint32_t kd = smb + 65536  + s * 32768;
        uint32_t vd = smb + 131072 + s * 32768;
#pragma unroll
        for (int t = 0; t < 4; t++) {
            int e = tid + t * 256, r = e >> 4, c4 = e & 15;
            uint32_t off = r * 256 + ((c4 ^ (r & 7)) << 4);
            int go = r * DH + c4 * 8;
            cp16(kd + off,         kh + go);
            cp16(kd + 16384 + off, kl + go);
            cp16(vd + off,         vh + go);
            cp16(vd + 16384 + off, vl + go);
        }
        asm volatile("cp.async.commit_group;" ::: "memory");
    };
    ldkv(0, 0);

    float m_i[2] = {-1e30f, -1e30f}, l_i[2] = {0.f, 0.f};
    float o[16][4];
#pragma unroll
    for (int ni = 0; ni < 16; ni++)
#pragma unroll
        for (int c = 0; c < 4; c++) o[ni][c] = 0.f;

    const int kb_max = 2 * qb + 1;
    for (int kb = 0; kb <= kb_max; ++kb) {
        asm volatile("cp.async.wait_group 0;" ::: "memory");
        __syncthreads();
        if (kb < kb_max) ldkv((kb + 1) & 1, kb + 1);

        const uint32_t sK = smb + 65536  + (kb & 1) * 32768;
        const uint32_t sV = smb + 131072 + (kb & 1) * 32768;

        float sf[8][4];
#pragma unroll
        for (int ni = 0; ni < 8; ni++)
#pragma unroll
            for (int c = 0; c < 4; c++) sf[ni][c] = 0.f;

#pragma unroll
        for (int ks = 0; ks < 8; ks++) {
            uint32_t ah[4], al[4], bh2[8][2], bl2[8][2];
            {
                int r = m0 + (lane & 15), c4 = ks * 2 + (lane >> 4);
                uint32_t off = r * 256 + ((c4 ^ (r & 7)) << 4);
                ldsm4(ah, smb + off);
                ldsm4(al, smb + 32768 + off);
            }
#pragma unroll
            for (int nb = 0; nb < 4; nb++) {
                int r = nb * 16 + (lane & 15), c4 = ks * 2 + (lane >> 4);
                uint32_t off = r * 256 + ((c4 ^ (r & 7)) << 4);
                uint32_t t4r[4];
                ldsm4(t4r, sK + off);
                bh2[nb*2][0] = t4r[0]; bh2[nb*2][1] = t4r[2];
                bh2[nb*2+1][0] = t4r[1]; bh2[nb*2+1][1] = t4r[3];
                ldsm4(t4r, sK + 16384 + off);
                bl2[nb*2][0] = t4r[0]; bl2[nb*2][1] = t4r[2];
                bl2[nb*2+1][0] = t4r[1]; bl2[nb*2+1][1] = t4r[3];
            }
#pragma unroll
            for (int ni = 0; ni < 8; ni++) mma16816(sf[ni], ah, bh2[ni]);
#pragma unroll
            for (int ni = 0; ni < 8; ni++) mma16816(sf[ni], al, bh2[ni]);
#pragma unroll
            for (int ni = 0; ni < 8; ni++) mma16816(sf[ni], ah, bl2[ni]);
        }

        const bool near = (kb * 64 + 63) > (qb * 128 + m0);
#pragma unroll
        for (int rr = 0; rr < 2; rr++) {
            int row_g = qb * 128 + m0 + g + rr * 8;
            float mx = -1e30f;
#pragma unroll
            for (int ni = 0; ni < 8; ni++)
#pragma unroll
                for (int c = 0; c < 2; c++) {
                    float v = sf[ni][rr * 2 + c] * scale;
                    if (near && (kb * 64 + ni * 8 + tig * 2 + c) > row_g) v = -1e30f;
                    sf[ni][rr * 2 + c] = v;
                    mx = fmaxf(mx, v);
                }
            mx = fmaxf(mx, __shfl_xor_sync(0xffffffffu, mx, 1));
            mx = fmaxf(mx, __shfl_xor_sync(0xffffffffu, mx, 2));
            float mn    = fmaxf(m_i[rr], mx);
            float alpha = __expf(m_i[rr] - mn);
            m_i[rr] = mn;
            float rs = 0.f;
#pragma unroll
            for (int ni = 0; ni < 8; ni++)
#pragma unroll
                for (int c = 0; c < 2; c++) {
                    float p = __expf(sf[ni][rr * 2 + c] - mn);
                    sf[ni][rr * 2 + c] = p;
                    rs += p;
                }
            rs += __shfl_xor_sync(0xffffffffu, rs, 1);
            rs += __shfl_xor_sync(0xffffffffu, rs, 2);
            l_i[rr] = l_i[rr] * alpha + rs;
#pragma unroll
            for (int ni = 0; ni < 16; ni++) {
                o[ni][rr * 2]     *= alpha;
                o[ni][rr * 2 + 1] *= alpha;
            }
        }

#pragma unroll
        for (int ks = 0; ks < 4; ks++) {
            uint32_t ph[4], pl[4];
            pack_hl(sf[2*ks][0],   sf[2*ks][1],   ph[0], pl[0]);
            pack_hl(sf[2*ks][2],   sf[2*ks][3],   ph[1], pl[1]);
            pack_hl(sf[2*ks+1][0], sf[2*ks+1][1], ph[2], pl[2]);
            pack_hl(sf[2*ks+1][2], sf[2*ks+1][3], ph[3], pl[3]);
#pragma unroll
            for (int nb = 0; nb < 8; nb++) {
                int row = ks * 16 + (lane & 7) + ((lane & 16) >> 1);
                int ch  = nb * 2 + ((lane >> 3) & 1);
                uint32_t off = row * 256 + ((ch ^ (row & 7)) << 4);
                uint32_t t4r[4], bvh[2][2], bvl[2][2];
                ldsm4t(t4r, sV + off);
                bvh[0][0] = t4r[0]; bvh[0][1] = t4r[2];
                bvh[1][0] = t4r[1]; bvh[1][1] = t4r[3];
                ldsm4t(t4r, sV + 16384 + off);
                bvl[0][0] = t4r[0]; bvl[0][1] = t4r[2];
                bvl[1][0] = t4r[1]; bvl[1][1] = t4r[3];
                mma16816(o[nb*2],   ph, bvh[0]);
                mma16816(o[nb*2+1], ph, bvh[1]);
                mma16816(o[nb*2],   pl, bvh[0]);
                mma16816(o[nb*2+1], pl, bvh[1]);
                mma16816(o[nb*2],   ph, bvl[0]);
                mma16816(o[nb*2+1], ph, bvl[1]);
            }
        }
    }

    const float hval = hsc[h];
#pragma unroll
    for (int rr = 0; rr < 2; rr++) {
        float inv = hval / l_i[rr];
        int n = qb * 128 + m0 + g + rr * 8;
        size_t base = ((size_t)(b * NSEQ + n)) * DIMM + h * DH;
#pragma unroll
        for (int ni = 0; ni < 16; ni++) {
            int col = ni * 8 + tig * 2;
            float v0 = o[ni][rr * 2] * inv, v1 = o[ni][rr * 2 + 1] * inv;
            __half h0 = __float2half(v0), h1 = __float2half(v1);
            *(__half2*)(OhF + base + col) = __halves2half2(h0, h1);
            *(__half2*)(OlF + base + col) =
                __halves2half2(__float2half(v0 - __half2float(h0)),
                               __float2half(v1 - __half2float(h1)));
        }
    }
}

// ---------------- launch ---------------------------------------------------
extern "C" void kernel_launch(void* const* d_in, const int* in_sizes, int n_in,
                              void* d_out, int out_size)
{
    const float* x   = (const float*)d_in[0];
    const float* Wq  = (const float*)d_in[1];
    const float* Wk  = (const float*)d_in[2];
    const float* Wv  = (const float*)d_in[3];
    const float* Wo  = (const float*)d_in[4];
    const float* hsc = (const float*)d_in[5];
    float* out = (float*)d_out;

    float *Qh, *Kh, *Vh, *cs;
    __half *xhF, *xlF, *WcF, *WoF, *OhF, *OlF;
    __nv_bfloat16 *Qbh, *Qbl, *Kbh, *Kbl, *Vbh, *Vbl;
    cudaGetSymbolAddress((void**)&Qh,  g_Qh);
    cudaGetSymbolAddress((void**)&Kh,  g_Kh);
    cudaGetSymbolAddress((void**)&Vh,  g_Vh);
    cudaGetSymbolAddress((void**)&cs,  g_cs);
    cudaGetSymbolAddress((void**)&xhF, g_xhF);  cudaGetSymbolAddress((void**)&xlF, g_xlF);
    cudaGetSymbolAddress((void**)&WcF, g_WcF);
    cudaGetSymbolAddress((void**)&WoF, g_WoF);
    cudaGetSymbolAddress((void**)&OhF, g_OhF);  cudaGetSymbolAddress((void**)&OlF, g_OlF);
    cudaGetSymbolAddress((void**)&Qbh, g_Qbh);  cudaGetSymbolAddress((void**)&Qbl, g_Qbl);
    cudaGetSymbolAddress((void**)&Kbh, g_Kbh);  cudaGetSymbolAddress((void**)&Kbl, g_Kbl);
    cudaGetSymbolAddress((void**)&Vbh, g_Vbh);  cudaGetSymbolAddress((void**)&Vbl, g_Vbl);

    // launches 1..3: prep
    rope_table<<<(NSEQ * 64 + 255) / 256, 256>>>(cs);
    prep_split_f16<<<(MTOT * KDIM / 4 + 255) / 256, 256>>>(x, xhF, xlF, MTOT * KDIM / 4);
    wtrans_all<<<dim3(64, 64, 4), 256>>>(Wq, Wk, Wv, Wo, WcF, WoF);

    // launch 4 (profiled slot): merged QKV projection, fp16 2-pass
    const int gsm = 147456;     // 3 stages x 48KB
    cudaFuncSetAttribute(gemm_f16<1>, cudaFuncAttributeMaxDynamicSharedMemorySize, gsm);
    cudaFuncSetAttribute(gemm_f16<0>, cudaFuncAttributeMaxDynamicSharedMemorySize, gsm);
    gemm_f16<1><<<dim3(24, 32), 256, gsm>>>(xhF, xlF, WcF, Qh, Kh, Vh);

    // launch 5: rope Q/K + V split (bf16 hi/lo for flash)
    post_all<<<22528, 256>>>(Qh, Kh, Vh, cs, Qbh, Qbl, Kbh, Kbl, Vbh, Vbl);

    // launch 6: tensor-core flash attention (bf16 3-pass, writes fp16 hi/lo O)
    const int fsm = 196608;
    cudaFuncSetAttribute(flash_tc, cudaFuncAttributeMaxDynamicSharedMemorySize, fsm);
    flash_tc<<<dim3(8, B_SZ * NH), 256, fsm>>>(Qbh, Qbl, Kbh, Kbl, Vbh, Vbl,
                                               hsc, OhF, OlF);

    // launch 7: output projection, fp16 2-pass
    gemm_f16<0><<<dim3(16, 32), 256, gsm>>>(OhF, OlF, WoF, out, nullptr, nullptr);
}

// round 16
// speedup vs baseline: 1.4696x; 1.1741x over previous
#include <cuda_runtime.h>
#include <cuda_bf16.h>
#include <cuda_fp16.h>
#include <math.h>
#include <stdint.h>

#define B_SZ  4
#define NSEQ  1024
#define DIMM  2048
#define KDIM  2048
#define NH    16
#define NKV   4
#define DH    128
#define MTOT  (B_SZ * NSEQ)

// ---------------- scratch (device globals: no allocation allowed) ----------
__device__ float g_Qh[B_SZ * NH  * NSEQ * DH];     // fp32 [b,h,n,d] (pre-rope)
__device__ float g_Kh[B_SZ * NKV * NSEQ * DH];
__device__ __half g_xhF[MTOT * KDIM], g_xlF[MTOT * KDIM];          // x fp16 hi/lo
__device__ __half g_WcF[3072 * KDIM];                              // Wq|Wk|Wv ^T fp16
__device__ __half g_WoF[2048 * KDIM];                              // Wo^T fp16
__device__ __half g_OhF[MTOT * DIMM], g_OlF[MTOT * DIMM];          // attn out fp16 hi/lo
__device__ __half g_QfF[B_SZ * NH  * NSEQ * DH];                   // rotated Q fp16
__device__ __half g_KfF[B_SZ * NKV * NSEQ * DH];                   // rotated K fp16
__device__ __half g_VfF[B_SZ * NKV * NSEQ * DH];                   // V fp16 (from gemm)
__device__ float g_cs[NSEQ * 64 * 2];              // rope cos/sin table

// ---------------- helpers ---------------------------------------------------
__device__ __forceinline__ uint32_t cvta_s(const void* p) {
    uint32_t a;
    asm("{ .reg .u64 t; cvta.to.shared.u64 t, %1; cvt.u32.u64 %0, t; }"
        : "=r"(a) : "l"(p));
    return a;
}
__device__ __forceinline__ void cp16(uint32_t dst, const void* src) {
    asm volatile("cp.async.cg.shared.global [%0], [%1], 16;"
                 :: "r"(dst), "l"(src) : "memory");
}
__device__ __forceinline__ void ldsm4(uint32_t* r, uint32_t addr) {
    asm volatile("ldmatrix.sync.aligned.m8n8.x4.shared.b16 {%0,%1,%2,%3}, [%4];"
                 : "=r"(r[0]), "=r"(r[1]), "=r"(r[2]), "=r"(r[3]) : "r"(addr));
}
__device__ __forceinline__ void ldsm4t(uint32_t* r, uint32_t addr) {
    asm volatile("ldmatrix.sync.aligned.m8n8.x4.trans.shared.b16 {%0,%1,%2,%3}, [%4];"
                 : "=r"(r[0]), "=r"(r[1]), "=r"(r[2]), "=r"(r[3]) : "r"(addr));
}
__device__ __forceinline__ void mma16816h(float* d, const uint32_t* a,
                                          const uint32_t* b) {
    asm volatile(
        "mma.sync.aligned.m16n8k16.row.col.f32.f16.f16.f32 "
        "{%0,%1,%2,%3}, {%4,%5,%6,%7}, {%8,%9}, {%0,%1,%2,%3};"
        : "+f"(d[0]), "+f"(d[1]), "+f"(d[2]), "+f"(d[3])
        : "r"(a[0]), "r"(a[1]), "r"(a[2]), "r"(a[3]), "r"(b[0]), "r"(b[1]));
}
__device__ __forceinline__ uint32_t pack_h2(float v0, float v1) {
    __half2 h = __halves2half2(__float2half(v0), __float2half(v1));
    return *reinterpret_cast<uint32_t*>(&h);
}

// ---------------- prep kernels ---------------------------------------------
__global__ void rope_table(float* __restrict__ cs)
{
    int idx = blockIdx.x * blockDim.x + threadIdx.x;
    if (idx >= NSEQ * 64) return;
    int i = idx & 63, n = idx >> 6;
    double invf = exp(-(double)i * 0.14391156831212787);
    double s, c;
    sincos((double)n * invf, &s, &c);
    cs[idx * 2]     = (float)c;
    cs[idx * 2 + 1] = (float)s;
}

__global__ __launch_bounds__(256) void prep_split_f16(const float* __restrict__ x,
                                                      __half* __restrict__ hi,
                                                      __half* __restrict__ lo,
                                                      int n4)
{
    int idx = blockIdx.x * blockDim.x + threadIdx.x;
    if (idx >= n4) return;
    float4 v = ((const float4*)x)[idx];
    __half h0 = __float2half(v.x), h1 = __float2half(v.y);
    __half h2 = __float2half(v.z), h3 = __float2half(v.w);
    __half2* hp = (__half2*)hi;
    __half2* lp = (__half2*)lo;
    hp[2*idx]   = __halves2half2(h0, h1);
    hp[2*idx+1] = __halves2half2(h2, h3);
    lp[2*idx]   = __halves2half2(__float2half(v.x - __half2float(h0)),
                                 __float2half(v.y - __half2float(h1)));
    lp[2*idx+1] = __halves2half2(__float2half(v.z - __half2float(h2)),
                                 __float2half(v.w - __half2float(h3)));
}

__global__ __launch_bounds__(256) void wtrans_all(
    const float* __restrict__ Wq, const float* __restrict__ Wk,
    const float* __restrict__ Wv, const float* __restrict__ Wo,
    __half* wc, __half* wof)
{
    const float* W; __half* th; int N;
    switch (blockIdx.z) {
        case 0:  W = Wq; th = wc;               N = 2048; break;
        case 1:  W = Wk; th = wc + 2048 * KDIM; N = 512;  break;
        case 2:  W = Wv; th = wc + 2560 * KDIM; N = 512;  break;
        default: W = Wo; th = wof;              N = 2048; break;
    }
    int n0 = blockIdx.x * 32, k0 = blockIdx.y * 32;
    if (n0 >= N) return;
    __shared__ float t[32][33];
    int tx = threadIdx.x & 31, ty = threadIdx.x >> 5;
#pragma unroll
    for (int j = 0; j < 32; j += 8)
        t[ty + j][tx] = W[(size_t)(k0 + ty + j) * N + n0 + tx];
    __syncthreads();
#pragma unroll
    for (int j = 0; j < 32; j += 8)
        th[(size_t)(n0 + ty + j) * KDIM + k0 + tx] = __float2half(t[tx][ty + j]);
}

// ---------------- post_all: rope Q + rope K -> single fp16 -----------------
__global__ __launch_bounds__(256) void post_all(
    const float* __restrict__ Qh, const float* __restrict__ Kh,
    const float* __restrict__ cs,
    __half* __restrict__ Qf, __half* __restrict__ Kf)
{
    const int blk = blockIdx.x, tid = threadIdx.x;
    const float* src; __half* dst; int idx;
    if (blk < 16384) { src = Qh; dst = Qf; idx = blk * 256 + tid; }
    else             { src = Kh; dst = Kf; idx = (blk - 16384) * 256 + tid; }
    int i   = idx & 63;
    int n   = (idx >> 6) & 1023;
    int bhd = idx >> 16;
    float2 v = ((const float2*)cs)[n * 64 + i];
    size_t o0 = (size_t)bhd * (NSEQ * DH) + n * DH + i;
    float t1 = src[o0], t2 = src[o0 + 64];
    dst[o0]      = __float2half(t1 * v.x - t2 * v.y);
    dst[o0 + 64] = __float2half(t2 * v.x + t1 * v.y);
}

// ---------------- fp16 2-pass GEMM: 3-stage cp.async, 48KB/stage -----------
// MODE 1: QKV combined; Q/K -> fp32 head layout (rope next), V -> fp16 direct.
// MODE 0: plain fp32 [M][DIMM] (output projection).
template <int MODE>
__global__ __launch_bounds__(256)
void gemm_f16(const __half* __restrict__ Ahi, const __half* __restrict__ Alo,
              const __half* __restrict__ B,
              float* __restrict__ Cq, float* __restrict__ Ck,
              __half* __restrict__ Vf)
{
    extern __shared__ __align__(16) char smem[];
    const uint32_t sb0 = cvta_s(smem);

    const int tid  = threadIdx.x;
    const int wid  = tid >> 5, lane = tid & 31;
    const int wm   = wid & 3,  wn   = wid >> 2;
    const int am   = wm * 32,  bn0  = wn * 64;
    const int bm   = blockIdx.y * 128, bn = blockIdx.x * 128;

    const __half* srcs[3] = { Ahi + (size_t)bm * KDIM, Alo + (size_t)bm * KDIM,
                              B   + (size_t)bn * KDIM };

    const int lr[4] = { (tid + 0)   >> 3, (tid + 256) >> 3,
                        (tid + 512) >> 3, (tid + 768) >> 3 };
    const int lc[4] = { (tid + 0)   & 7,  (tid + 256) & 7,
                        (tid + 512) & 7,  (tid + 768) & 7 };

    float acc[2][8][4];
#pragma unroll
    for (int mi = 0; mi < 2; mi++)
#pragma unroll
        for (int ni = 0; ni < 8; ni++)
#pragma unroll
            for (int c = 0; c < 4; c++) acc[mi][ni][c] = 0.f;

    const int NT = KDIM / 64;

    auto load_stage = [&](int s, int kt) {
        uint32_t sb = sb0 + s * 49152;
#pragma unroll
        for (int tt = 0; tt < 3; tt++) {
            const __half* src = srcs[tt];
#pragma unroll
            for (int a = 0; a < 4; a++) {
                int r = lr[a], c4 = lc[a];
                uint32_t dst = sb + tt * 16384 + r * 128 + ((c4 ^ (r & 7)) << 4);
                cp16(dst, src + (size_t)r * KDIM + kt + c4 * 8);
            }
        }
        asm volatile("cp.async.commit_group;" ::: "memory");
    };

    load_stage(0, 0);
    load_stage(1, 64);

    int buf = 0;
    for (int it = 0; it < NT; ++it) {
        if (it + 1 < NT) {
            asm volatile("cp.async.wait_group 1;" ::: "memory");
        } else {
            asm volatile("cp.async.wait_group 0;" ::: "memory");
        }
        __syncthreads();
        if (it + 2 < NT) {
            int nb = buf + 2; if (nb >= 3) nb -= 3;
            load_stage(nb, (it + 2) * 64);
        }

        const uint32_t sb = sb0 + buf * 49152;
#pragma unroll
        for (int ks = 0; ks < 4; ks++) {
            uint32_t ah[2][4], al[2][4], bf[8][2];
#pragma unroll
            for (int mi = 0; mi < 2; mi++) {
                int r  = am + mi * 16 + (lane & 15);
                int c4 = ks * 2 + (lane >> 4);
                uint32_t off = r * 128 + ((c4 ^ (r & 7)) << 4);
                ldsm4(ah[mi], sb + off);
                ldsm4(al[mi], sb + 16384 + off);
            }
#pragma unroll
            for (int nb2 = 0; nb2 < 4; nb2++) {
                int r  = bn0 + nb2 * 16 + (lane & 15);
                int c4 = ks * 2 + (lane >> 4);
                uint32_t off = r * 128 + ((c4 ^ (r & 7)) << 4);
                uint32_t t[4];
                ldsm4(t, sb + 32768 + off);
                bf[nb2*2][0]   = t[0]; bf[nb2*2][1]   = t[2];
                bf[nb2*2+1][0] = t[1]; bf[nb2*2+1][1] = t[3];
            }
#pragma unroll
            for (int mi = 0; mi < 2; mi++)
#pragma unroll
                for (int ni = 0; ni < 8; ni++) mma16816h(acc[mi][ni], ah[mi], bf[ni]);
#pragma unroll
            for (int mi = 0; mi < 2; mi++)
#pragma unroll
                for (int ni = 0; ni < 8; ni++) mma16816h(acc[mi][ni], al[mi], bf[ni]);
        }
        if (++buf == 3) buf = 0;
    }

    const int g = lane >> 2, tig = lane & 3;
    if (MODE == 1 && bn >= 2560) {
        // V tile -> fp16 head layout directly (no fp32 round-trip)
        int h = (bn - 2560) >> 7;
#pragma unroll
        for (int mi = 0; mi < 2; mi++)
#pragma unroll
            for (int ni = 0; ni < 8; ni++) {
                int d  = bn0 + ni * 8 + tig * 2;
                int r0 = bm + am + mi * 16 + g, r1 = r0 + 8;
                int b0 = r0 >> 10, n0 = r0 & 1023;
                int b1 = r1 >> 10, n1 = r1 & 1023;
                __half* p0 = Vf + (((size_t)(b0 * NKV + h)) * NSEQ + n0) * DH + d;
                __half* p1 = Vf + (((size_t)(b1 * NKV + h)) * NSEQ + n1) * DH + d;
                *(__half2*)p0 = __halves2half2(__float2half(acc[mi][ni][0]),
                                               __float2half(acc[mi][ni][1]));
                *(__half2*)p1 = __halves2half2(__float2half(acc[mi][ni][2]),
                                               __float2half(acc[mi][ni][3]));
            }
        return;
    }
    float* base; int h = 0, Hout = 0;
    if (MODE == 1) {
        if (bn < 2048) { base = Cq; h = bn >> 7;          Hout = NH;  }
        else           { base = Ck; h = (bn - 2048) >> 7; Hout = NKV; }
    } else {
        base = Cq;
    }
#pragma unroll
    for (int mi = 0; mi < 2; mi++) {
#pragma unroll
        for (int ni = 0; ni < 8; ni++) {
            int d   = bn0 + ni * 8 + tig * 2;
            int r0  = bm + am + mi * 16 + g;
            int r1  = r0 + 8;
            float* p0;
            float* p1;
            if (MODE == 1) {
                int b0 = r0 >> 10, n0 = r0 & 1023;
                int b1 = r1 >> 10, n1 = r1 & 1023;
                p0 = base + (((size_t)(b0 * Hout + h)) * NSEQ + n0) * DH + d;
                p1 = base + (((size_t)(b1 * Hout + h)) * NSEQ + n1) * DH + d;
            } else {
                p0 = base + (size_t)r0 * DIMM + bn + d;
                p1 = base + (size_t)r1 * DIMM + bn + d;
            }
            *(float2*)p0 = make_float2(acc[mi][ni][0], acc[mi][ni][1]);
            *(float2*)p1 = make_float2(acc[mi][ni][2], acc[mi][ni][3]);
        }
    }
}

// ---------------- fp16 single-pass causal flash attention ------------------
// q-tile 128 x kv-tile 64, 8 warps; Q/K/V/P single fp16, fp32 accum.
// smem (96KB): Q 0..32K | K stages 32K+s*16K | V stages 64K+s*16K
__global__ __launch_bounds__(256)
void flash_tc(const __half* __restrict__ Qf, const __half* __restrict__ Kf,
              const __half* __restrict__ Vf, const float* __restrict__ hsc,
              __half* __restrict__ OhF, __half* __restrict__ OlF)
{
    extern __shared__ __align__(16) char smc[];
    const uint32_t smb = cvta_s(smc);
    const int tid = threadIdx.x, wid = tid >> 5, lane = tid & 31;
    const int qb = 7 - blockIdx.x;
    const int bh = blockIdx.y, b = bh >> 4, h = bh & 15, kvh = h >> 2;
    const int m0 = wid * 16;
    const int g = lane >> 2, tig = lane & 3;
    const float scale = 0.08838834764831845f;

    const __half* Qg = Qf + ((size_t)(b * NH + h) * NSEQ + qb * 128) * DH;
    const size_t kvb = (size_t)(b * NKV + kvh) * NSEQ * DH;

#pragma unroll
    for (int t = 0; t < 8; t++) {
        int e = tid + t * 256, r = e >> 4, c4 = e & 15;
        uint32_t off = r * 256 + ((c4 ^ (r & 7)) << 4);
        cp16(smb + off, Qg + r * DH + c4 * 8);
    }
    auto ldkv = [&](int s, int kb) {
        const __half* kg = Kf + kvb + (size_t)kb * 64 * DH;
        const __half* vg = Vf + kvb + (size_t)kb * 64 * DH;
        uint32_t kd = smb + 32768 + s * 16384;
        uint32_t vd = smb + 65536 + s * 16384;
#pragma unroll
        for (int t = 0; t < 4; t++) {
            int e = tid + t * 256, r = e >> 4, c4 = e & 15;
            uint32_t off = r * 256 + ((c4 ^ (r & 7)) << 4);
            int go = r * DH + c4 * 8;
            cp16(kd + off, kg + go);
            cp16(vd + off, vg + go);
        }
        asm volatile("cp.async.commit_group;" ::: "memory");
    };
    ldkv(0, 0);   // commits Q + KV0 as one group

    float m_i[2] = {-1e30f, -1e30f}, l_i[2] = {0.f, 0.f};
    float o[16][4];
#pragma unroll
    for (int ni = 0; ni < 16; ni++)
#pragma unroll
        for (int c = 0; c < 4; c++) o[ni][c] = 0.f;

    const int kb_max = 2 * qb + 1;
    for (int kb = 0; kb <= kb_max; ++kb) {
        asm volatile("cp.async.wait_group 0;" ::: "memory");
        __syncthreads();
        if (kb < kb_max) ldkv((kb + 1) & 1, kb + 1);

        const uint32_t sK = smb + 32768 + (kb & 1) * 16384;
        const uint32_t sV = smb + 65536 + (kb & 1) * 16384;

        // ---- S = Q K^T, single fp16 pass, warp tile 16x64 ----
        float sf[8][4];
#pragma unroll
        for (int ni = 0; ni < 8; ni++)
#pragma unroll
            for (int c = 0; c < 4; c++) sf[ni][c] = 0.f;

#pragma unroll
        for (int ks = 0; ks < 8; ks++) {
            uint32_t ah[4], bh2[8][2];
            {
                int r = m0 + (lane & 15), c4 = ks * 2 + (lane >> 4);
                uint32_t off = r * 256 + ((c4 ^ (r & 7)) << 4);
                ldsm4(ah, smb + off);
            }
#pragma unroll
            for (int nb = 0; nb < 4; nb++) {
                int r = nb * 16 + (lane & 15), c4 = ks * 2 + (lane >> 4);
                uint32_t off = r * 256 + ((c4 ^ (r & 7)) << 4);
                uint32_t t4r[4];
                ldsm4(t4r, sK + off);
                bh2[nb*2][0] = t4r[0]; bh2[nb*2][1] = t4r[2];
                bh2[nb*2+1][0] = t4r[1]; bh2[nb*2+1][1] = t4r[3];
            }
#pragma unroll
            for (int ni = 0; ni < 8; ni++) mma16816h(sf[ni], ah, bh2[ni]);
        }

        // ---- online softmax ----
        const bool near = (kb * 64 + 63) > (qb * 128 + m0);
#pragma unroll
        for (int rr = 0; rr < 2; rr++) {
            int row_g = qb * 128 + m0 + g + rr * 8;
            float mx = -1e30f;
#pragma unroll
            for (int ni = 0; ni < 8; ni++)
#pragma unroll
                for (int c = 0; c < 2; c++) {
                    float v = sf[ni][rr * 2 + c] * scale;
                    if (near && (kb * 64 + ni * 8 + tig * 2 + c) > row_g) v = -1e30f;
                    sf[ni][rr * 2 + c] = v;
                    mx = fmaxf(mx, v);
                }
            mx = fmaxf(mx, __shfl_xor_sync(0xffffffffu, mx, 1));
            mx = fmaxf(mx, __shfl_xor_sync(0xffffffffu, mx, 2));
            float mn    = fmaxf(m_i[rr], mx);
            float alpha = __expf(m_i[rr] - mn);
            m_i[rr] = mn;
            float rs = 0.f;
#pragma unroll
            for (int ni = 0; ni < 8; ni++)
#pragma unroll
                for (int c = 0; c < 2; c++) {
                    float p = __expf(sf[ni][rr * 2 + c] - mn);
                    sf[ni][rr * 2 + c] = p;
                    rs += p;
                }
            rs += __shfl_xor_sync(0xffffffffu, rs, 1);
            rs += __shfl_xor_sync(0xffffffffu, rs, 2);
            l_i[rr] = l_i[rr] * alpha + rs;
#pragma unroll
            for (int ni = 0; ni < 16; ni++) {
                o[ni][rr * 2]     *= alpha;
                o[ni][rr * 2 + 1] *= alpha;
            }
        }

        // ---- O += P V, single fp16 pass, P packed in-register ----
#pragma unroll
        for (int ks = 0; ks < 4; ks++) {
            uint32_t ph[4];
            ph[0] = pack_h2(sf[2*ks][0],   sf[2*ks][1]);
            ph[1] = pack_h2(sf[2*ks][2],   sf[2*ks][3]);
            ph[2] = pack_h2(sf[2*ks+1][0], sf[2*ks+1][1]);
            ph[3] = pack_h2(sf[2*ks+1][2], sf[2*ks+1][3]);
#pragma unroll
            for (int nb = 0; nb < 8; nb++) {
                int row = ks * 16 + (lane & 7) + ((lane & 16) >> 1);
                int ch  = nb * 2 + ((lane >> 3) & 1);
                uint32_t off = row * 256 + ((ch ^ (row & 7)) << 4);
                uint32_t t4r[4], bvh[2][2];
                ldsm4t(t4r, sV + off);
                bvh[0][0] = t4r[0]; bvh[0][1] = t4r[2];
                bvh[1][0] = t4r[1]; bvh[1][1] = t4r[3];
                mma16816h(o[nb*2],   ph, bvh[0]);
                mma16816h(o[nb*2+1], ph, bvh[1]);
            }
        }
    }

    // ---- epilogue: normalize, head-scale, write fp16 hi/lo O ----
    const float hval = hsc[h];
#pragma unroll
    for (int rr = 0; rr < 2; rr++) {
        float inv = hval / l_i[rr];
        int n = qb * 128 + m0 + g + rr * 8;
        size_t base = ((size_t)(b * NSEQ + n)) * DIMM + h * DH;
#pragma unroll
        for (int ni = 0; ni < 16; ni++) {
            int col = ni * 8 + tig * 2;
            float v0 = o[ni][rr * 2] * inv, v1 = o[ni][rr * 2 + 1] * inv;
            __half h0 = __float2half(v0), h1 = __float2half(v1);
            *(__half2*)(OhF + base + col) = __halves2half2(h0, h1);
            *(__half2*)(OlF + base + col) =
                __halves2half2(__float2half(v0 - __half2float(h0)),
                               __float2half(v1 - __half2float(h1)));
        }
    }
}

// ---------------- launch ---------------------------------------------------
extern "C" void kernel_launch(void* const* d_in, const int* in_sizes, int n_in,
                              void* d_out, int out_size)
{
    const float* x   = (const float*)d_in[0];
    const float* Wq  = (const float*)d_in[1];
    const float* Wk  = (const float*)d_in[2];
    const float* Wv  = (const float*)d_in[3];
    const float* Wo  = (const float*)d_in[4];
    const float* hsc = (const float*)d_in[5];
    float* out = (float*)d_out;

    float *Qh, *Kh, *cs;
    __half *xhF, *xlF, *WcF, *WoF, *OhF, *OlF, *QfF, *KfF, *VfF;
    cudaGetSymbolAddress((void**)&Qh,  g_Qh);
    cudaGetSymbolAddress((void**)&Kh,  g_Kh);
    cudaGetSymbolAddress((void**)&cs,  g_cs);
    cudaGetSymbolAddress((void**)&xhF, g_xhF);  cudaGetSymbolAddress((void**)&xlF, g_xlF);
    cudaGetSymbolAddress((void**)&WcF, g_WcF);
    cudaGetSymbolAddress((void**)&WoF, g_WoF);
    cudaGetSymbolAddress((void**)&OhF, g_OhF);  cudaGetSymbolAddress((void**)&OlF, g_OlF);
    cudaGetSymbolAddress((void**)&QfF, g_QfF);
    cudaGetSymbolAddress((void**)&KfF, g_KfF);
    cudaGetSymbolAddress((void**)&VfF, g_VfF);

    // launches 1..3: prep
    rope_table<<<(NSEQ * 64 + 255) / 256, 256>>>(cs);
    prep_split_f16<<<(MTOT * KDIM / 4 + 255) / 256, 256>>>(x, xhF, xlF, MTOT * KDIM / 4);
    wtrans_all<<<dim3(64, 64, 4), 256>>>(Wq, Wk, Wv, Wo, WcF, WoF);

    // launch 4 (profiled slot): merged QKV projection, fp16 2-pass
    // (V written fp16 head-layout directly)
    const int gsm = 147456;     // 3 stages x 48KB
    cudaFuncSetAttribute(gemm_f16<1>, cudaFuncAttributeMaxDynamicSharedMemorySize, gsm);
    cudaFuncSetAttribute(gemm_f16<0>, cudaFuncAttributeMaxDynamicSharedMemorySize, gsm);
    gemm_f16<1><<<dim3(24, 32), 256, gsm>>>(xhF, xlF, WcF, Qh, Kh, VfF);

    // launch 5: rope Q/K -> single fp16
    post_all<<<20480, 256>>>(Qh, Kh, cs, QfF, KfF);

    // launch 6: fp16 single-pass flash attention (96KB smem)
    const int fsm = 98304;
    cudaFuncSetAttribute(flash_tc, cudaFuncAttributeMaxDynamicSharedMemorySize, fsm);
    flash_tc<<<dim3(8, B_SZ * NH), 256, fsm>>>(QfF, KfF, VfF, hsc, OhF, OlF);

    // launch 7: output projection, fp16 2-pass
    gemm_f16<0><<<dim3(16, 32), 256, gsm>>>(OhF, OlF, WoF, out, nullptr, nullptr);
}

// round 17
// speedup vs baseline: 2.5203x; 1.7150x over previous
#include <cuda_runtime.h>
#include <cuda_bf16.h>
#include <cuda_fp16.h>
#include <math.h>
#include <stdint.h>

#define B_SZ  4
#define NSEQ  1024
#define DIMM  2048
#define KDIM  2048
#define NH    16
#define NKV   4
#define DH    128
#define MTOT  (B_SZ * NSEQ)

// ---------------- scratch (device globals: no allocation allowed) ----------
__device__ float g_Qh[B_SZ * NH  * NSEQ * DH];     // fp32 [b,h,n,d] (pre-rope)
__device__ float g_Kh[B_SZ * NKV * NSEQ * DH];
__device__ __half g_xF [MTOT * KDIM];                              // x fp16
__device__ __half g_WcF[3072 * KDIM];                              // Wq|Wk|Wv ^T fp16
__device__ __half g_WoF[2048 * KDIM];                              // Wo^T fp16
__device__ __half g_OF [MTOT * DIMM];                              // attn out fp16
__device__ __half g_QfF[B_SZ * NH  * NSEQ * DH];                   // rotated Q fp16
__device__ __half g_KfF[B_SZ * NKV * NSEQ * DH];                   // rotated K fp16
__device__ __half g_VfF[B_SZ * NKV * NSEQ * DH];                   // V fp16 (from gemm)
__device__ float g_cs[NSEQ * 64 * 2];              // rope cos/sin table

// ---------------- helpers ---------------------------------------------------
__device__ __forceinline__ uint32_t cvta_s(const void* p) {
    uint32_t a;
    asm("{ .reg .u64 t; cvta.to.shared.u64 t, %1; cvt.u32.u64 %0, t; }"
        : "=r"(a) : "l"(p));
    return a;
}
__device__ __forceinline__ void cp16(uint32_t dst, const void* src) {
    asm volatile("cp.async.cg.shared.global [%0], [%1], 16;"
                 :: "r"(dst), "l"(src) : "memory");
}
__device__ __forceinline__ void ldsm4(uint32_t* r, uint32_t addr) {
    asm volatile("ldmatrix.sync.aligned.m8n8.x4.shared.b16 {%0,%1,%2,%3}, [%4];"
                 : "=r"(r[0]), "=r"(r[1]), "=r"(r[2]), "=r"(r[3]) : "r"(addr));
}
__device__ __forceinline__ void ldsm4t(uint32_t* r, uint32_t addr) {
    asm volatile("ldmatrix.sync.aligned.m8n8.x4.trans.shared.b16 {%0,%1,%2,%3}, [%4];"
                 : "=r"(r[0]), "=r"(r[1]), "=r"(r[2]), "=r"(r[3]) : "r"(addr));
}
__device__ __forceinline__ void mma16816h(float* d, const uint32_t* a,
                                          const uint32_t* b) {
    asm volatile(
        "mma.sync.aligned.m16n8k16.row.col.f32.f16.f16.f32 "
        "{%0,%1,%2,%3}, {%4,%5,%6,%7}, {%8,%9}, {%0,%1,%2,%3};"
        : "+f"(d[0]), "+f"(d[1]), "+f"(d[2]), "+f"(d[3])
        : "r"(a[0]), "r"(a[1]), "r"(a[2]), "r"(a[3]), "r"(b[0]), "r"(b[1]));
}
__device__ __forceinline__ uint32_t pack_h2(float v0, float v1) {
    __half2 h = __halves2half2(__float2half(v0), __float2half(v1));
    return *reinterpret_cast<uint32_t*>(&h);
}

// ---------------- prep kernels ---------------------------------------------
__global__ void rope_table(float* __restrict__ cs)
{
    int idx = blockIdx.x * blockDim.x + threadIdx.x;
    if (idx >= NSEQ * 64) return;
    int i = idx & 63, n = idx >> 6;
    double invf = exp(-(double)i * 0.14391156831212787);
    double s, c;
    sincos((double)n * invf, &s, &c);
    cs[idx * 2]     = (float)c;
    cs[idx * 2 + 1] = (float)s;
}

// x fp32 -> single fp16
__global__ __launch_bounds__(256) void prep_f16(const float* __restrict__ x,
                                                __half* __restrict__ o, int n4)
{
    int idx = blockIdx.x * blockDim.x + threadIdx.x;
    if (idx >= n4) return;
    float4 v = ((const float4*)x)[idx];
    __half2* op = (__half2*)o;
    op[2*idx]   = __halves2half2(__float2half(v.x), __float2half(v.y));
    op[2*idx+1] = __halves2half2(__float2half(v.z), __float2half(v.w));
}

__global__ __launch_bounds__(256) void wtrans_all(
    const float* __restrict__ Wq, const float* __restrict__ Wk,
    const float* __restrict__ Wv, const float* __restrict__ Wo,
    __half* wc, __half* wof)
{
    const float* W; __half* th; int N;
    switch (blockIdx.z) {
        case 0:  W = Wq; th = wc;               N = 2048; break;
        case 1:  W = Wk; th = wc + 2048 * KDIM; N = 512;  break;
        case 2:  W = Wv; th = wc + 2560 * KDIM; N = 512;  break;
        default: W = Wo; th = wof;              N = 2048; break;
    }
    int n0 = blockIdx.x * 32, k0 = blockIdx.y * 32;
    if (n0 >= N) return;
    __shared__ float t[32][33];
    int tx = threadIdx.x & 31, ty = threadIdx.x >> 5;
#pragma unroll
    for (int j = 0; j < 32; j += 8)
        t[ty + j][tx] = W[(size_t)(k0 + ty + j) * N + n0 + tx];
    __syncthreads();
#pragma unroll
    for (int j = 0; j < 32; j += 8)
        th[(size_t)(n0 + ty + j) * KDIM + k0 + tx] = __float2half(t[tx][ty + j]);
}

// ---------------- post_all: rope Q + rope K -> single fp16 -----------------
__global__ __launch_bounds__(256) void post_all(
    const float* __restrict__ Qh, const float* __restrict__ Kh,
    const float* __restrict__ cs,
    __half* __restrict__ Qf, __half* __restrict__ Kf)
{
    const int blk = blockIdx.x, tid = threadIdx.x;
    const float* src; __half* dst; int idx;
    if (blk < 16384) { src = Qh; dst = Qf; idx = blk * 256 + tid; }
    else             { src = Kh; dst = Kf; idx = (blk - 16384) * 256 + tid; }
    int i   = idx & 63;
    int n   = (idx >> 6) & 1023;
    int bhd = idx >> 16;
    float2 v = ((const float2*)cs)[n * 64 + i];
    size_t o0 = (size_t)bhd * (NSEQ * DH) + n * DH + i;
    float t1 = src[o0], t2 = src[o0 + 64];
    dst[o0]      = __float2half(t1 * v.x - t2 * v.y);
    dst[o0 + 64] = __float2half(t2 * v.x + t1 * v.y);
}

// ---------------- fp16 single-pass GEMM: 3-stage cp.async, 32KB/stage ------
// C = A @ B^T ; both single fp16, fp32 accumulate.
// MODE 1: QKV combined; Q/K -> fp32 head layout (rope next), V -> fp16 direct.
// MODE 0: plain fp32 [M][DIMM] (output projection).
template <int MODE>
__global__ __launch_bounds__(256)
void gemm_f16(const __half* __restrict__ A, const __half* __restrict__ B,
              float* __restrict__ Cq, float* __restrict__ Ck,
              __half* __restrict__ Vf)
{
    extern __shared__ __align__(16) char smem[];
    const uint32_t sb0 = cvta_s(smem);

    const int tid  = threadIdx.x;
    const int wid  = tid >> 5, lane = tid & 31;
    const int wm   = wid & 3,  wn   = wid >> 2;
    const int am   = wm * 32,  bn0  = wn * 64;
    const int bm   = blockIdx.y * 128, bn = blockIdx.x * 128;

    const __half* srcs[2] = { A + (size_t)bm * KDIM, B + (size_t)bn * KDIM };

    const int lr[4] = { (tid + 0)   >> 3, (tid + 256) >> 3,
                        (tid + 512) >> 3, (tid + 768) >> 3 };
    const int lc[4] = { (tid + 0)   & 7,  (tid + 256) & 7,
                        (tid + 512) & 7,  (tid + 768) & 7 };

    float acc[2][8][4];
#pragma unroll
    for (int mi = 0; mi < 2; mi++)
#pragma unroll
        for (int ni = 0; ni < 8; ni++)
#pragma unroll
            for (int c = 0; c < 4; c++) acc[mi][ni][c] = 0.f;

    const int NT = KDIM / 64;

    auto load_stage = [&](int s, int kt) {
        uint32_t sb = sb0 + s * 32768;
#pragma unroll
        for (int tt = 0; tt < 2; tt++) {
            const __half* src = srcs[tt];
#pragma unroll
            for (int a = 0; a < 4; a++) {
                int r = lr[a], c4 = lc[a];
                uint32_t dst = sb + tt * 16384 + r * 128 + ((c4 ^ (r & 7)) << 4);
                cp16(dst, src + (size_t)r * KDIM + kt + c4 * 8);
            }
        }
        asm volatile("cp.async.commit_group;" ::: "memory");
    };

    load_stage(0, 0);
    load_stage(1, 64);

    int buf = 0;
    for (int it = 0; it < NT; ++it) {
        if (it + 1 < NT) {
            asm volatile("cp.async.wait_group 1;" ::: "memory");
        } else {
            asm volatile("cp.async.wait_group 0;" ::: "memory");
        }
        __syncthreads();
        if (it + 2 < NT) {
            int nb = buf + 2; if (nb >= 3) nb -= 3;
            load_stage(nb, (it + 2) * 64);
        }

        const uint32_t sb = sb0 + buf * 32768;
#pragma unroll
        for (int ks = 0; ks < 4; ks++) {
            uint32_t ah[2][4], bf[8][2];
#pragma unroll
            for (int mi = 0; mi < 2; mi++) {
                int r  = am + mi * 16 + (lane & 15);
                int c4 = ks * 2 + (lane >> 4);
                uint32_t off = r * 128 + ((c4 ^ (r & 7)) << 4);
                ldsm4(ah[mi], sb + off);
            }
#pragma unroll
            for (int nb2 = 0; nb2 < 4; nb2++) {
                int r  = bn0 + nb2 * 16 + (lane & 15);
                int c4 = ks * 2 + (lane >> 4);
                uint32_t off = r * 128 + ((c4 ^ (r & 7)) << 4);
                uint32_t t[4];
                ldsm4(t, sb + 16384 + off);
                bf[nb2*2][0]   = t[0]; bf[nb2*2][1]   = t[2];
                bf[nb2*2+1][0] = t[1]; bf[nb2*2+1][1] = t[3];
            }
#pragma unroll
            for (int mi = 0; mi < 2; mi++)
#pragma unroll
                for (int ni = 0; ni < 8; ni++) mma16816h(acc[mi][ni], ah[mi], bf[ni]);
        }
        if (++buf == 3) buf = 0;
    }

    const int g = lane >> 2, tig = lane & 3;
    if (MODE == 1 && bn >= 2560) {
        // V tile -> fp16 head layout directly
        int h = (bn - 2560) >> 7;
#pragma unroll
        for (int mi = 0; mi < 2; mi++)
#pragma unroll
            for (int ni = 0; ni < 8; ni++) {
                int d  = bn0 + ni * 8 + tig * 2;
                int r0 = bm + am + mi * 16 + g, r1 = r0 + 8;
                int b0 = r0 >> 10, n0 = r0 & 1023;
                int b1 = r1 >> 10, n1 = r1 & 1023;
                __half* p0 = Vf + (((size_t)(b0 * NKV + h)) * NSEQ + n0) * DH + d;
                __half* p1 = Vf + (((size_t)(b1 * NKV + h)) * NSEQ + n1) * DH + d;
                *(__half2*)p0 = __halves2half2(__float2half(acc[mi][ni][0]),
                                               __float2half(acc[mi][ni][1]));
                *(__half2*)p1 = __halves2half2(__float2half(acc[mi][ni][2]),
                                               __float2half(acc[mi][ni][3]));
            }
        return;
    }
    float* base; int h = 0, Hout = 0;
    if (MODE == 1) {
        if (bn < 2048) { base = Cq; h = bn >> 7;          Hout = NH;  }
        else           { base = Ck; h = (bn - 2048) >> 7; Hout = NKV; }
    } else {
        base = Cq;
    }
#pragma unroll
    for (int mi = 0; mi < 2; mi++) {
#pragma unroll
        for (int ni = 0; ni < 8; ni++) {
            int d   = bn0 + ni * 8 + tig * 2;
            int r0  = bm + am + mi * 16 + g;
            int r1  = r0 + 8;
            float* p0;
            float* p1;
            if (MODE == 1) {
                int b0 = r0 >> 10, n0 = r0 & 1023;
                int b1 = r1 >> 10, n1 = r1 & 1023;
                p0 = base + (((size_t)(b0 * Hout + h)) * NSEQ + n0) * DH + d;
                p1 = base + (((size_t)(b1 * Hout + h)) * NSEQ + n1) * DH + d;
            } else {
                p0 = base + (size_t)r0 * DIMM + bn + d;
                p1 = base + (size_t)r1 * DIMM + bn + d;
            }
            *(float2*)p0 = make_float2(acc[mi][ni][0], acc[mi][ni][1]);
            *(float2*)p1 = make_float2(acc[mi][ni][2], acc[mi][ni][3]);
        }
    }
}

// ---------------- fp16 single-pass causal flash attention ------------------
// q-tile 128 x kv-tile 64, 8 warps; Q/K/V/P single fp16, fp32 accum.
// smem (96KB): Q 0..32K | K stages 32K+s*16K | V stages 64K+s*16K
__global__ __launch_bounds__(256)
void flash_tc(const __half* __restrict__ Qf, const __half* __restrict__ Kf,
              const __half* __restrict__ Vf, const float* __restrict__ hsc,
              __half* __restrict__ OF)
{
    extern __shared__ __align__(16) char smc[];
    const uint32_t smb = cvta_s(smc);
    const int tid = threadIdx.x, wid = tid >> 5, lane = tid & 31;
    const int qb = 7 - blockIdx.x;
    const int bh = blockIdx.y, b = bh >> 4, h = bh & 15, kvh = h >> 2;
    const int m0 = wid * 16;
    const int g = lane >> 2, tig = lane & 3;
    const float scale = 0.08838834764831845f;

    const __half* Qg = Qf + ((size_t)(b * NH + h) * NSEQ + qb * 128) * DH;
    const size_t kvb = (size_t)(b * NKV + kvh) * NSEQ * DH;

#pragma unroll
    for (int t = 0; t < 8; t++) {
        int e = tid + t * 256, r = e >> 4, c4 = e & 15;
        uint32_t off = r * 256 + ((c4 ^ (r & 7)) << 4);
        cp16(smb + off, Qg + r * DH + c4 * 8);
    }
    auto ldkv = [&](int s, int kb) {
        const __half* kg = Kf + kvb + (size_t)kb * 64 * DH;
        const __half* vg = Vf + kvb + (size_t)kb * 64 * DH;
        uint32_t kd = smb + 32768 + s * 16384;
        uint32_t vd = smb + 65536 + s * 16384;
#pragma unroll
        for (int t = 0; t < 4; t++) {
            int e = tid + t * 256, r = e >> 4, c4 = e & 15;
            uint32_t off = r * 256 + ((c4 ^ (r & 7)) << 4);
            int go = r * DH + c4 * 8;
            cp16(kd + off, kg + go);
            cp16(vd + off, vg + go);
        }
        asm volatile("cp.async.commit_group;" ::: "memory");
    };
    ldkv(0, 0);

    float m_i[2] = {-1e30f, -1e30f}, l_i[2] = {0.f, 0.f};
    float o[16][4];
#pragma unroll
    for (int ni = 0; ni < 16; ni++)
#pragma unroll
        for (int c = 0; c < 4; c++) o[ni][c] = 0.f;

    const int kb_max = 2 * qb + 1;
    for (int kb = 0; kb <= kb_max; ++kb) {
        asm volatile("cp.async.wait_group 0;" ::: "memory");
        __syncthreads();
        if (kb < kb_max) ldkv((kb + 1) & 1, kb + 1);

        const uint32_t sK = smb + 32768 + (kb & 1) * 16384;
        const uint32_t sV = smb + 65536 + (kb & 1) * 16384;

        float sf[8][4];
#pragma unroll
        for (int ni = 0; ni < 8; ni++)
#pragma unroll
            for (int c = 0; c < 4; c++) sf[ni][c] = 0.f;

#pragma unroll
        for (int ks = 0; ks < 8; ks++) {
            uint32_t ah[4], bh2[8][2];
            {
                int r = m0 + (lane & 15), c4 = ks * 2 + (lane >> 4);
                uint32_t off = r * 256 + ((c4 ^ (r & 7)) << 4);
                ldsm4(ah, smb + off);
            }
#pragma unroll
            for (int nb = 0; nb < 4; nb++) {
                int r = nb * 16 + (lane & 15), c4 = ks * 2 + (lane >> 4);
                uint32_t off = r * 256 + ((c4 ^ (r & 7)) << 4);
                uint32_t t4r[4];
                ldsm4(t4r, sK + off);
                bh2[nb*2][0] = t4r[0]; bh2[nb*2][1] = t4r[2];
                bh2[nb*2+1][0] = t4r[1]; bh2[nb*2+1][1] = t4r[3];
            }
#pragma unroll
            for (int ni = 0; ni < 8; ni++) mma16816h(sf[ni], ah, bh2[ni]);
        }

        const bool near = (kb * 64 + 63) > (qb * 128 + m0);
#pragma unroll
        for (int rr = 0; rr < 2; rr++) {
            int row_g = qb * 128 + m0 + g + rr * 8;
            float mx = -1e30f;
#pragma unroll
            for (int ni = 0; ni < 8; ni++)
#pragma unroll
                for (int c = 0; c < 2; c++) {
                    float v = sf[ni][rr * 2 + c] * scale;
                    if (near && (kb * 64 + ni * 8 + tig * 2 + c) > row_g) v = -1e30f;
                    sf[ni][rr * 2 + c] = v;
                    mx = fmaxf(mx, v);
                }
            mx = fmaxf(mx, __shfl_xor_sync(0xffffffffu, mx, 1));
            mx = fmaxf(mx, __shfl_xor_sync(0xffffffffu, mx, 2));
            float mn    = fmaxf(m_i[rr], mx);
            float alpha = __expf(m_i[rr] - mn);
            m_i[rr] = mn;
            float rs = 0.f;
#pragma unroll
            for (int ni = 0; ni < 8; ni++)
#pragma unroll
                for (int c = 0; c < 2; c++) {
                    float p = __expf(sf[ni][rr * 2 + c] - mn);
                    sf[ni][rr * 2 + c] = p;
                    rs += p;
                }
            rs += __shfl_xor_sync(0xffffffffu, rs, 1);
            rs += __shfl_xor_sync(0xffffffffu, rs, 2);
            l_i[rr] = l_i[rr] * alpha + rs;
#pragma unroll
            for (int ni = 0; ni < 16; ni++) {
                o[ni][rr * 2]     *= alpha;
                o[ni][rr * 2 + 1] *= alpha;
            }
        }

#pragma unroll
        for (int ks = 0; ks < 4; ks++) {
            uint32_t ph[4];
            ph[0] = pack_h2(sf[2*ks][0],   sf[2*ks][1]);
            ph[1] = pack_h2(sf[2*ks][2],   sf[2*ks][3]);
            ph[2] = pack_h2(sf[2*ks+1][0], sf[2*ks+1][1]);
            ph[3] = pack_h2(sf[2*ks+1][2], sf[2*ks+1][3]);
#pragma unroll
            for (int nb = 0; nb < 8; nb++) {
                int row = ks * 16 + (lane & 7) + ((lane & 16) >> 1);
                int ch  = nb * 2 + ((lane >> 3) & 1);
                uint32_t off = row * 256 + ((ch ^ (row & 7)) << 4);
                uint32_t t4r[4], bvh[2][2];
                ldsm4t(t4r, sV + off);
                bvh[0][0] = t4r[0]; bvh[0][1] = t4r[2];
                bvh[1][0] = t4r[1]; bvh[1][1] = t4r[3];
                mma16816h(o[nb*2],   ph, bvh[0]);
                mma16816h(o[nb*2+1], ph, bvh[1]);
            }
        }
    }

    // epilogue: normalize, head-scale, write single fp16 O
    const float hval = hsc[h];
#pragma unroll
    for (int rr = 0; rr < 2; rr++) {
        float inv = hval / l_i[rr];
        int n = qb * 128 + m0 + g + rr * 8;
        size_t base = ((size_t)(b * NSEQ + n)) * DIMM + h * DH;
#pragma unroll
        for (int ni = 0; ni < 16; ni++) {
            int col = ni * 8 + tig * 2;
            *(__half2*)(OF + base + col) =
                __halves2half2(__float2half(o[ni][rr * 2] * inv),
                               __float2half(o[ni][rr * 2 + 1] * inv));
        }
    }
}

// ---------------- launch ---------------------------------------------------
extern "C" void kernel_launch(void* const* d_in, const int* in_sizes, int n_in,
                              void* d_out, int out_size)
{
    const float* x   = (const float*)d_in[0];
    const float* Wq  = (const float*)d_in[1];
    const float* Wk  = (const float*)d_in[2];
    const float* Wv  = (const float*)d_in[3];
    const float* Wo  = (const float*)d_in[4];
    const float* hsc = (const float*)d_in[5];
    float* out = (float*)d_out;

    float *Qh, *Kh, *cs;
    __half *xF, *WcF, *WoF, *OF, *QfF, *KfF, *VfF;
    cudaGetSymbolAddress((void**)&Qh,  g_Qh);
    cudaGetSymbolAddress((void**)&Kh,  g_Kh);
    cudaGetSymbolAddress((void**)&cs,  g_cs);
    cudaGetSymbolAddress((void**)&xF,  g_xF);
    cudaGetSymbolAddress((void**)&WcF, g_WcF);
    cudaGetSymbolAddress((void**)&WoF, g_WoF);
    cudaGetSymbolAddress((void**)&OF,  g_OF);
    cudaGetSymbolAddress((void**)&QfF, g_QfF);
    cudaGetSymbolAddress((void**)&KfF, g_KfF);
    cudaGetSymbolAddress((void**)&VfF, g_VfF);

    // launches 1..3: prep
    rope_table<<<(NSEQ * 64 + 255) / 256, 256>>>(cs);
    prep_f16<<<(MTOT * KDIM / 4 + 255) / 256, 256>>>(x, xF, MTOT * KDIM / 4);
    wtrans_all<<<dim3(64, 64, 4), 256>>>(Wq, Wk, Wv, Wo, WcF, WoF);

    // launch 4 (profiled slot): merged QKV projection, fp16 single-pass
    const int gsm = 98304;      // 3 stages x 32KB
    cudaFuncSetAttribute(gemm_f16<1>, cudaFuncAttributeMaxDynamicSharedMemorySize, gsm);
    cudaFuncSetAttribute(gemm_f16<0>, cudaFuncAttributeMaxDynamicSharedMemorySize, gsm);
    gemm_f16<1><<<dim3(24, 32), 256, gsm>>>(xF, WcF, Qh, Kh, VfF);

    // launch 5: rope Q/K -> single fp16
    post_all<<<20480, 256>>>(Qh, Kh, cs, QfF, KfF);

    // launch 6: fp16 single-pass flash attention (96KB smem)
    const int fsm = 98304;
    cudaFuncSetAttribute(flash_tc, cudaFuncAttributeMaxDynamicSharedMemorySize, fsm);
    flash_tc<<<dim3(8, B_SZ * NH), 256, fsm>>>(QfF, KfF, VfF, hsc, OF);

    // launch 7: output projection, fp16 single-pass
    gemm_f16<0><<<dim3(16, 32), 256, gsm>>>(OF, WoF, out, nullptr, nullptr);
}